// round 1
// baseline (speedup 1.0000x reference)
#include <cuda_runtime.h>
#include <cstdint>

// ---------------- problem constants ----------------
#define BB   1024
#define NN   128
#define FF   16
#define GG   48
#define HH   6
#define DD   8
#define GRUU 256
#define EMBB 128
#define XG   (NN*GG)       // 6144 flattened GAT output per batch
#define G3   (3*GRUU)      // 768

// ---------------- scratch (no allocation allowed) ----------------
__device__ float g_x  [BB*XG];     // GAT output, flattened [B, 6144]
__device__ float g_gi [BB*G3];     // GRU gate pre-activations
__device__ float g_h  [BB*GRUU];
__device__ float g_h2 [BB*GRUU];
__device__ float g_hln[BB*GRUU];
__device__ float g_emb[BB*EMBB];

// =======================================================================
// GAT kernel: one CTA per batch. Whole 2-layer GAT + LN/ReLU + residual
// computed in shared memory. Attention uses the rank-1 exp trick:
//   exp(lrelu(ei+ej)) = (ei+ej>0) ? exp(ei)*exp(ej) : exp(.01ei)*exp(.01ej)
// =======================================================================

__device__ __forceinline__ void gat_attention(
    const float* __restrict__ sh, const float* __restrict__ sei,
    const float* __restrict__ sej, const float* __restrict__ sPj,
    const float* __restrict__ sQj, const unsigned* __restrict__ smask,
    float* __restrict__ sy, int tid)
{
    #pragma unroll 1
    for (int rep = 0; rep < 3; rep++) {
        int r  = rep * 256 + tid;           // 768 rows = (head, node i)
        int hd = r >> 7, i = r & 127;       // warp shares one head -> smem broadcasts
        float eiv = sei[r];
        float Pi = __expf(eiv), Qi = __expf(0.01f * eiv);
        float acc[8];
        #pragma unroll
        for (int d = 0; d < 8; d++) acc[d] = 0.f;
        float ssum = 0.f;
        const unsigned* mrow = smask + (i << 2);
        const float* ejp = sej + (hd << 7);
        const float* Pjp = sPj + (hd << 7);
        const float* Qjp = sQj + (hd << 7);
        const float* hp  = sh  + (hd << 10);
        #pragma unroll 1
        for (int jw = 0; jw < 4; jw++) {
            unsigned bits = mrow[jw];
            #pragma unroll
            for (int jj = 0; jj < 32; jj++) {
                int j = (jw << 5) | jj;
                float s = eiv + ejp[j];
                float w = (s > 0.f) ? (Pi * Pjp[j]) : (Qi * Qjp[j]);
                w = (bits & (1u << jj)) ? w : 0.f;
                ssum += w;
                float4 h0 = *(const float4*)(hp + (j << 3));
                float4 h1 = *(const float4*)(hp + (j << 3) + 4);
                acc[0] = fmaf(w, h0.x, acc[0]); acc[1] = fmaf(w, h0.y, acc[1]);
                acc[2] = fmaf(w, h0.z, acc[2]); acc[3] = fmaf(w, h0.w, acc[3]);
                acc[4] = fmaf(w, h1.x, acc[4]); acc[5] = fmaf(w, h1.y, acc[5]);
                acc[6] = fmaf(w, h1.z, acc[6]); acc[7] = fmaf(w, h1.w, acc[7]);
            }
        }
        float inv = 1.0f / ssum;
        float* o = sy + i * 49 + (hd << 3);
        #pragma unroll
        for (int d = 0; d < 8; d++) o[d] = acc[d] * inv;
    }
}

// LayerNorm over all [N,G] of one batch, + ReLU. sy has row stride 49.
__device__ __forceinline__ void ln2d_apply(
    float* __restrict__ sy, const float* __restrict__ gamma,
    const float* __restrict__ beta, float* __restrict__ sred,
    int tid, float* __restrict__ gout)
{
    float s = 0.f, q = 0.f;
    for (int t = tid; t < XG; t += 256) {
        int n = t / 48, c = t - n * 48;
        float v = sy[n * 49 + c];
        s += v; q += v * v;
    }
    #pragma unroll
    for (int o = 16; o; o >>= 1) {
        s += __shfl_xor_sync(0xffffffffu, s, o);
        q += __shfl_xor_sync(0xffffffffu, q, o);
    }
    int wid = tid >> 5;
    if ((tid & 31) == 0) { sred[wid] = s; sred[8 + wid] = q; }
    __syncthreads();
    if (tid == 0) {
        float S = 0.f, Q = 0.f;
        #pragma unroll
        for (int i = 0; i < 8; i++) { S += sred[i]; Q += sred[8 + i]; }
        float m   = S * (1.f / (float)XG);
        float var = Q * (1.f / (float)XG) - m * m;
        sred[16] = m;
        sred[17] = rsqrtf(var + 1e-5f);
    }
    __syncthreads();
    float m = sred[16], rs = sred[17];
    for (int t = tid; t < XG; t += 256) {
        int n = t / 48, c = t - n * 48;
        float v = (sy[n * 49 + c] - m) * rs * gamma[t] + beta[t];
        v = fmaxf(v, 0.f);
        if (gout) gout[t] = v; else sy[n * 49 + c] = v;
    }
}

__global__ __launch_bounds__(256)
void gat_kernel(const float* __restrict__ X,  const int* __restrict__ A,
                const float* __restrict__ W1, const float* __restrict__ a1,
                const float* __restrict__ W2, const float* __restrict__ a2,
                const float* __restrict__ Wr, const float* __restrict__ br,
                const float* __restrict__ g1, const float* __restrict__ b1,
                const float* __restrict__ g2, const float* __restrict__ b2)
{
    extern __shared__ float sm[];
    float*    sX    = sm;               // 128*17 = 2176 (padded rows)
    float*    sh    = sX  + 2176;       // 6*128*8 = 6144
    float*    sy    = sh  + 6144;       // 128*49  = 6272 (padded)
    float*    sei   = sy  + 6272;       // 768
    float*    sej   = sei + 768;        // 768
    float*    sPj   = sej + 768;        // 768
    float*    sQj   = sPj + 768;        // 768
    float*    sW    = sQj + 768;        // 2304 (max of W1/W2/Wr)
    float*    sa    = sW  + 2304;       // 96
    float*    sred  = sa  + 96;         // 20
    unsigned* smask = (unsigned*)(sred + 20); // 512 words

    int b = blockIdx.x, tid = threadIdx.x;

    // ---- load X (padded stride 17 to kill LDS bank conflicts) ----
    const float* Xb = X + (size_t)b * (NN * FF);
    for (int t = tid; t < NN * FF; t += 256)
        sX[(t >> 4) * 17 + (t & 15)] = Xb[t];

    // ---- adjacency -> bitmask via ballot ----
    {
        const int* Ab = A + (size_t)b * (NN * NN);
        int lane = tid & 31, wid = tid >> 5;
        for (int w = wid; w < 512; w += 8) {
            int i = w >> 2, j0 = (w & 3) << 5;
            unsigned bits = __ballot_sync(0xffffffffu, Ab[(i << 7) + j0 + lane] != 0);
            if (lane == 0) smask[w] = bits;
        }
    }
    for (int t = tid; t < HH * FF * DD; t += 256) sW[t] = W1[t];
    if (tid < HH * 2 * DD) sa[tid] = a1[tid];
    __syncthreads();

    // ---- layer 1: h = X@W1, scores, per-node exps ----
    for (int t = tid; t < HH * NN; t += 256) {
        int hd = t >> 7, n = t & 127;
        float acc[8];
        #pragma unroll
        for (int d = 0; d < 8; d++) acc[d] = 0.f;
        const float* w = sW + hd * (FF * DD);
        const float* x = sX + n * 17;
        #pragma unroll
        for (int f = 0; f < FF; f++) {
            float xv = x[f];
            #pragma unroll
            for (int d = 0; d < 8; d++) acc[d] = fmaf(xv, w[(f << 3) + d], acc[d]);
        }
        const float* av = sa + (hd << 4);
        float ei = 0.f, ej = 0.f;
        #pragma unroll
        for (int d = 0; d < 8; d++) { ei = fmaf(acc[d], av[d], ei); ej = fmaf(acc[d], av[8 + d], ej); }
        #pragma unroll
        for (int d = 0; d < 8; d++) sh[(t << 3) + d] = acc[d];
        sei[t] = ei; sej[t] = ej;
        sPj[t] = __expf(ej); sQj[t] = __expf(0.01f * ej);
    }
    __syncthreads();
    gat_attention(sh, sei, sej, sPj, sQj, smask, sy, tid);
    __syncthreads();
    ln2d_apply(sy, g1, b1, sred, tid, nullptr);
    __syncthreads();

    // ---- layer 2 weights ----
    for (int t = tid; t < HH * GG * DD; t += 256) sW[t] = W2[t];
    if (tid < HH * 2 * DD) sa[tid] = a2[tid];
    __syncthreads();

    // ---- layer 2: h2 = y@W2, scores ----
    for (int t = tid; t < HH * NN; t += 256) {
        int hd = t >> 7, n = t & 127;
        float acc[8];
        #pragma unroll
        for (int d = 0; d < 8; d++) acc[d] = 0.f;
        const float* w = sW + hd * (GG * DD);
        const float* x = sy + n * 49;
        #pragma unroll
        for (int f = 0; f < GG; f++) {
            float xv = x[f];
            #pragma unroll
            for (int d = 0; d < 8; d++) acc[d] = fmaf(xv, w[(f << 3) + d], acc[d]);
        }
        const float* av = sa + (hd << 4);
        float ei = 0.f, ej = 0.f;
        #pragma unroll
        for (int d = 0; d < 8; d++) { ei = fmaf(acc[d], av[d], ei); ej = fmaf(acc[d], av[8 + d], ej); }
        #pragma unroll
        for (int d = 0; d < 8; d++) sh[(t << 3) + d] = acc[d];
        sei[t] = ei; sej[t] = ej;
        sPj[t] = __expf(ej); sQj[t] = __expf(0.01f * ej);
    }
    __syncthreads();
    gat_attention(sh, sei, sej, sPj, sQj, smask, sy, tid);   // overwrites sy
    __syncthreads();

    // ---- residual: sy += X@Wr + br ----
    for (int t = tid; t < FF * GG; t += 256) sW[t] = Wr[t];
    if (tid < GG) sa[tid] = br[tid];
    __syncthreads();
    for (int t = tid; t < XG; t += 256) {
        int n = t / 48, c = t - n * 48;
        float accv = sa[c];
        const float* x = sX + n * 17;
        #pragma unroll
        for (int f = 0; f < FF; f++) accv = fmaf(x[f], sW[f * 48 + c], accv);
        sy[n * 49 + c] += accv;
    }
    __syncthreads();
    ln2d_apply(sy, g2, b2, sred, tid, g_x + (size_t)b * XG);
}

// =======================================================================
// Generic SGEMM: C[M,N] = A[M,K] * B^T + bias, optional ReLU.
// B element (n,k) at Bm[n*ldbn + k*ldbk] (supports [N,K] and [K,N]).
// BM=BN=64, BK=16, 128 threads, 4x8 microtile, register prefetch.
// Requires M%64==0, N%64==0, K%16==0 (true for all calls here).
// =======================================================================
__global__ __launch_bounds__(128)
void gemm_k(const float* __restrict__ A, const float* __restrict__ Bm,
            const float* __restrict__ bias, float* __restrict__ C,
            int M, int N, int K, int ldbn, int ldbk, int act)
{
    __shared__ float As[16][68];
    __shared__ float Bs[16][68];
    int tid  = threadIdx.x;
    int bm   = blockIdx.y << 6, bn = blockIdx.x << 6;
    int trow = (tid >> 3) << 2;    // 16 row-threads * 4 rows
    int tcol = (tid & 7) << 3;     // 8 col-threads * 8 cols

    float acc[4][8];
    #pragma unroll
    for (int r = 0; r < 4; r++)
        #pragma unroll
        for (int c = 0; c < 8; c++) acc[r][c] = 0.f;

    float4 pa[2]; float pb[8];
    #pragma unroll
    for (int q = 0; q < 2; q++) {
        int idx = tid + (q << 7); int m = idx >> 2, kq = (idx & 3) << 2;
        pa[q] = *(const float4*)(A + (size_t)(bm + m) * K + kq);
    }
    #pragma unroll
    for (int q = 0; q < 8; q++) {
        int idx = tid + (q << 7); int n = idx >> 4, k = idx & 15;
        pb[q] = Bm[(size_t)(bn + n) * ldbn + (size_t)k * ldbk];
    }

    for (int kt = 0; kt < K; kt += 16) {
        #pragma unroll
        for (int q = 0; q < 2; q++) {
            int idx = tid + (q << 7); int m = idx >> 2, kq = (idx & 3) << 2;
            As[kq][m] = pa[q].x; As[kq + 1][m] = pa[q].y;
            As[kq + 2][m] = pa[q].z; As[kq + 3][m] = pa[q].w;
        }
        #pragma unroll
        for (int q = 0; q < 8; q++) {
            int idx = tid + (q << 7); int n = idx >> 4, k = idx & 15;
            Bs[k][n] = pb[q];
        }
        __syncthreads();
        int ktn = kt + 16;
        if (ktn < K) {
            #pragma unroll
            for (int q = 0; q < 2; q++) {
                int idx = tid + (q << 7); int m = idx >> 2, kq = (idx & 3) << 2;
                pa[q] = *(const float4*)(A + (size_t)(bm + m) * K + ktn + kq);
            }
            #pragma unroll
            for (int q = 0; q < 8; q++) {
                int idx = tid + (q << 7); int n = idx >> 4, k = idx & 15;
                pb[q] = Bm[(size_t)(bn + n) * ldbn + (size_t)(ktn + k) * ldbk];
            }
        }
        #pragma unroll
        for (int kk = 0; kk < 16; kk++) {
            float4 a0 = *(const float4*)&As[kk][trow];
            float4 b0 = *(const float4*)&Bs[kk][tcol];
            float4 b1 = *(const float4*)&Bs[kk][tcol + 4];
            float av[4] = {a0.x, a0.y, a0.z, a0.w};
            float bv[8] = {b0.x, b0.y, b0.z, b0.w, b1.x, b1.y, b1.z, b1.w};
            #pragma unroll
            for (int r = 0; r < 4; r++)
                #pragma unroll
                for (int c = 0; c < 8; c++)
                    acc[r][c] = fmaf(av[r], bv[c], acc[r][c]);
        }
        __syncthreads();
    }

    #pragma unroll
    for (int c = 0; c < 8; c++) {
        int n = bn + tcol + c;
        float bv = bias ? bias[n] : 0.f;
        #pragma unroll
        for (int r = 0; r < 4; r++) {
            float v = acc[r][c] + bv;
            if (act) v = fmaxf(v, 0.f);
            C[(size_t)(bm + trow + r) * N + n] = v;
        }
    }
}

// =======================================================================
// GRU gates with hidden state == 0:  gh = bhh,  h = (1-z)*n
// =======================================================================
__global__ __launch_bounds__(256)
void gru_gates(const float* __restrict__ gi, const float* __restrict__ bhh,
               float* __restrict__ h)
{
    int idx = blockIdx.x * 256 + threadIdx.x;   // B*256
    int b = idx >> 8, j = idx & 255;
    const float* g = gi + (size_t)b * G3;
    float r = 1.f / (1.f + __expf(-(g[j]        + bhh[j])));
    float z = 1.f / (1.f + __expf(-(g[256 + j]  + bhh[256 + j])));
    float n = tanhf(g[512 + j] + r * bhh[512 + j]);
    h[idx] = (1.f - z) * n;
}

// =======================================================================
// LayerNorm over GRU dim (256), one CTA per batch row
// =======================================================================
__global__ __launch_bounds__(256)
void ln1d_k(const float* __restrict__ h, const float* __restrict__ g,
            const float* __restrict__ b, float* __restrict__ o)
{
    __shared__ float s1[8], s2[8], mv[2];
    int row = blockIdx.x, tid = threadIdx.x;
    float v = h[(size_t)row * GRUU + tid];
    float s = v, q = v * v;
    #pragma unroll
    for (int off = 16; off; off >>= 1) {
        s += __shfl_xor_sync(0xffffffffu, s, off);
        q += __shfl_xor_sync(0xffffffffu, q, off);
    }
    if ((tid & 31) == 0) { s1[tid >> 5] = s; s2[tid >> 5] = q; }
    __syncthreads();
    if (tid == 0) {
        float S = 0.f, Q = 0.f;
        #pragma unroll
        for (int i = 0; i < 8; i++) { S += s1[i]; Q += s2[i]; }
        float m = S * (1.f / 256.f);
        float var = Q * (1.f / 256.f) - m * m;
        mv[0] = m; mv[1] = rsqrtf(var + 1e-5f);
    }
    __syncthreads();
    o[(size_t)row * GRUU + tid] = (v - mv[0]) * mv[1] * g[tid] + b[tid];
}

// =======================================================================
// host launcher
// =======================================================================
extern "C" void kernel_launch(void* const* d_in, const int* in_sizes, int n_in,
                              void* d_out, int out_size)
{
    const float* X    = (const float*)d_in[0];
    const int*   A    = (const int*)  d_in[1];
    const float* W1   = (const float*)d_in[2];
    const float* a1   = (const float*)d_in[3];
    const float* W2   = (const float*)d_in[4];
    const float* a2   = (const float*)d_in[5];
    const float* Wr   = (const float*)d_in[6];
    const float* br   = (const float*)d_in[7];
    const float* g1   = (const float*)d_in[8];
    const float* b1   = (const float*)d_in[9];
    const float* g2   = (const float*)d_in[10];
    const float* b2   = (const float*)d_in[11];
    const float* Wih0 = (const float*)d_in[12];
    const float* bih0 = (const float*)d_in[14];
    const float* bhh0 = (const float*)d_in[15];
    const float* Wih1 = (const float*)d_in[16];
    const float* bih1 = (const float*)d_in[18];
    const float* bhh1 = (const float*)d_in[19];
    const float* Wih2 = (const float*)d_in[20];
    const float* bih2 = (const float*)d_in[22];
    const float* bhh2 = (const float*)d_in[23];
    const float* gng  = (const float*)d_in[24];
    const float* gnb  = (const float*)d_in[25];
    const float* We   = (const float*)d_in[26];
    const float* be   = (const float*)d_in[27];
    const float* Wp   = (const float*)d_in[28];
    const float* bp   = (const float*)d_in[29];
    float* out = (float*)d_out;

    float *px, *pgi, *ph, *ph2, *phln, *pemb;
    cudaGetSymbolAddress((void**)&px,   g_x);
    cudaGetSymbolAddress((void**)&pgi,  g_gi);
    cudaGetSymbolAddress((void**)&ph,   g_h);
    cudaGetSymbolAddress((void**)&ph2,  g_h2);
    cudaGetSymbolAddress((void**)&phln, g_hln);
    cudaGetSymbolAddress((void**)&pemb, g_emb);

    const int GAT_SMEM = (2176 + 6144 + 6272 + 4 * 768 + 2304 + 96 + 20 + 512) * 4;
    cudaFuncSetAttribute(gat_kernel, cudaFuncAttributeMaxDynamicSharedMemorySize, GAT_SMEM);

    gat_kernel<<<BB, 256, GAT_SMEM>>>(X, A, W1, a1, W2, a2, Wr, br, g1, b1, g2, b2);

    dim3 gGru(G3 / 64, BB / 64);                 // (12, 16)
    gemm_k<<<gGru, 128>>>(px,  Wih0, bih0, pgi, BB, G3, XG,   XG,   1, 0);
    gru_gates<<<BB, 256>>>(pgi, bhh0, ph);
    gemm_k<<<gGru, 128>>>(ph,  Wih1, bih1, pgi, BB, G3, GRUU, GRUU, 1, 0);
    gru_gates<<<BB, 256>>>(pgi, bhh1, ph2);
    gemm_k<<<gGru, 128>>>(ph2, Wih2, bih2, pgi, BB, G3, GRUU, GRUU, 1, 0);
    gru_gates<<<BB, 256>>>(pgi, bhh2, ph);

    ln1d_k<<<BB, 256>>>(ph, gng, gnb, phln);

    float* embp = (out_size >= 2 * BB * EMBB) ? (out + (size_t)BB * EMBB) : pemb;
    dim3 gHead(EMBB / 64, BB / 64);              // (2, 16)
    // emb = relu(hln @ We + be); We is [K=256, N=128] -> ldbn=1, ldbk=128
    gemm_k<<<gHead, 128>>>(phln, We, be, embp, BB, EMBB, GRUU, 1, EMBB, 1);
    // pred = emb @ Wp + bp; Wp is [K=128, N=128] -> ldbn=1, ldbk=128
    gemm_k<<<gHead, 128>>>(embp, Wp, bp, out, BB, NN, EMBB, 1, NN, 0);
}

// round 3
// speedup vs baseline: 1.4347x; 1.4347x over previous
#include <cuda_runtime.h>
#include <cstdint>

// ---------------- problem constants ----------------
#define BB   1024
#define NN   128
#define FF   16
#define GG   48
#define HH   6
#define DD   8
#define GRUU 256
#define EMBB 128
#define XG   (NN*GG)       // 6144
#define G3   (3*GRUU)      // 768

// ---------------- scratch (no allocation allowed) ----------------
__device__ uint32_t g_xhi [BB*XG];
__device__ uint32_t g_xlo [BB*XG];
__device__ uint32_t g_whi [G3*XG];      // reused for all weight splits
__device__ uint32_t g_wlo [G3*XG];
__device__ float    g_gi  [BB*G3];
__device__ float    g_h   [BB*GRUU];
__device__ uint32_t g_hhi [BB*GRUU];
__device__ uint32_t g_hlo [BB*GRUU];
__device__ uint32_t g_lnhi[BB*GRUU];
__device__ uint32_t g_lnlo[BB*GRUU];
__device__ uint32_t g_ehi [BB*EMBB];
__device__ uint32_t g_elo [BB*EMBB];
__device__ float    g_emb [BB*EMBB];

// ---------------- tf32 helpers ----------------
__device__ __forceinline__ void tf32split(float v, uint32_t& h, uint32_t& l) {
    uint32_t hb; asm("cvt.rna.tf32.f32 %0, %1;" : "=r"(hb) : "f"(v));
    float lv = v - __uint_as_float(hb);
    uint32_t lb; asm("cvt.rna.tf32.f32 %0, %1;" : "=r"(lb) : "f"(lv));
    h = hb; l = lb;
}

__device__ __forceinline__ void mma_tf32(float* c, const uint32_t* a, const uint32_t* b) {
    asm volatile("mma.sync.aligned.m16n8k8.row.col.f32.tf32.tf32.f32 "
        "{%0,%1,%2,%3}, {%4,%5,%6,%7}, {%8,%9}, {%0,%1,%2,%3};\n"
        : "+f"(c[0]), "+f"(c[1]), "+f"(c[2]), "+f"(c[3])
        : "r"(a[0]), "r"(a[1]), "r"(a[2]), "r"(a[3]), "r"(b[0]), "r"(b[1]));
}

// =======================================================================
// GAT kernel (unchanged math from R1; epilogue writes tf32 splits)
// =======================================================================
__device__ __forceinline__ void gat_attention(
    const float* __restrict__ sh, const float* __restrict__ sei,
    const float* __restrict__ sej, const float* __restrict__ sPj,
    const float* __restrict__ sQj, const unsigned* __restrict__ smask,
    float* __restrict__ sy, int tid)
{
    #pragma unroll 1
    for (int rep = 0; rep < 3; rep++) {
        int r  = rep * 256 + tid;
        int hd = r >> 7, i = r & 127;
        float eiv = sei[r];
        float Pi = __expf(eiv), Qi = __expf(0.01f * eiv);
        float acc[8];
        #pragma unroll
        for (int d = 0; d < 8; d++) acc[d] = 0.f;
        float ssum = 0.f;
        const unsigned* mrow = smask + (i << 2);
        const float* ejp = sej + (hd << 7);
        const float* Pjp = sPj + (hd << 7);
        const float* Qjp = sQj + (hd << 7);
        const float* hp  = sh  + (hd << 10);
        #pragma unroll 1
        for (int jw = 0; jw < 4; jw++) {
            unsigned bits = mrow[jw];
            #pragma unroll
            for (int jj = 0; jj < 32; jj++) {
                int j = (jw << 5) | jj;
                float s = eiv + ejp[j];
                float w = (s > 0.f) ? (Pi * Pjp[j]) : (Qi * Qjp[j]);
                w = (bits & (1u << jj)) ? w : 0.f;
                ssum += w;
                float4 h0 = *(const float4*)(hp + (j << 3));
                float4 h1 = *(const float4*)(hp + (j << 3) + 4);
                acc[0] = fmaf(w, h0.x, acc[0]); acc[1] = fmaf(w, h0.y, acc[1]);
                acc[2] = fmaf(w, h0.z, acc[2]); acc[3] = fmaf(w, h0.w, acc[3]);
                acc[4] = fmaf(w, h1.x, acc[4]); acc[5] = fmaf(w, h1.y, acc[5]);
                acc[6] = fmaf(w, h1.z, acc[6]); acc[7] = fmaf(w, h1.w, acc[7]);
            }
        }
        float inv = 1.0f / ssum;
        float* o = sy + i * 49 + (hd << 3);
        #pragma unroll
        for (int d = 0; d < 8; d++) o[d] = acc[d] * inv;
    }
}

__device__ __forceinline__ void ln2d_apply(
    float* __restrict__ sy, const float* __restrict__ gamma,
    const float* __restrict__ beta, float* __restrict__ sred,
    int tid, uint32_t* __restrict__ ghi, uint32_t* __restrict__ glo)
{
    float s = 0.f, q = 0.f;
    for (int t = tid; t < XG; t += 256) {
        int n = t / 48, c = t - n * 48;
        float v = sy[n * 49 + c];
        s += v; q += v * v;
    }
    #pragma unroll
    for (int o = 16; o; o >>= 1) {
        s += __shfl_xor_sync(0xffffffffu, s, o);
        q += __shfl_xor_sync(0xffffffffu, q, o);
    }
    int wid = tid >> 5;
    if ((tid & 31) == 0) { sred[wid] = s; sred[8 + wid] = q; }
    __syncthreads();
    if (tid == 0) {
        float S = 0.f, Q = 0.f;
        #pragma unroll
        for (int i = 0; i < 8; i++) { S += sred[i]; Q += sred[8 + i]; }
        float m   = S * (1.f / (float)XG);
        float var = Q * (1.f / (float)XG) - m * m;
        sred[16] = m;
        sred[17] = rsqrtf(var + 1e-5f);
    }
    __syncthreads();
    float m = sred[16], rs = sred[17];
    for (int t = tid; t < XG; t += 256) {
        int n = t / 48, c = t - n * 48;
        float v = (sy[n * 49 + c] - m) * rs * gamma[t] + beta[t];
        v = fmaxf(v, 0.f);
        if (ghi) { uint32_t hb, lb; tf32split(v, hb, lb); ghi[t] = hb; glo[t] = lb; }
        else sy[n * 49 + c] = v;
    }
}

__global__ __launch_bounds__(256)
void gat_kernel(const float* __restrict__ X,  const int* __restrict__ A,
                const float* __restrict__ W1, const float* __restrict__ a1,
                const float* __restrict__ W2, const float* __restrict__ a2,
                const float* __restrict__ Wr, const float* __restrict__ br,
                const float* __restrict__ g1, const float* __restrict__ b1,
                const float* __restrict__ g2, const float* __restrict__ b2)
{
    extern __shared__ float sm[];
    float*    sX    = sm;               // 2176
    float*    sh    = sX  + 2176;       // 6144
    float*    sy    = sh  + 6144;       // 6272
    float*    sei   = sy  + 6272;       // 768
    float*    sej   = sei + 768;        // 768
    float*    sPj   = sej + 768;        // 768
    float*    sQj   = sPj + 768;        // 768
    float*    sW    = sQj + 768;        // 2304
    float*    sa    = sW  + 2304;       // 96
    float*    sred  = sa  + 96;         // 20
    unsigned* smask = (unsigned*)(sred + 20); // 512

    int b = blockIdx.x, tid = threadIdx.x;

    const float* Xb = X + (size_t)b * (NN * FF);
    for (int t = tid; t < NN * FF; t += 256)
        sX[(t >> 4) * 17 + (t & 15)] = Xb[t];

    {
        const int* Ab = A + (size_t)b * (NN * NN);
        int lane = tid & 31, wid = tid >> 5;
        for (int w = wid; w < 512; w += 8) {
            int i = w >> 2, j0 = (w & 3) << 5;
            unsigned bits = __ballot_sync(0xffffffffu, Ab[(i << 7) + j0 + lane] != 0);
            if (lane == 0) smask[w] = bits;
        }
    }
    for (int t = tid; t < HH * FF * DD; t += 256) sW[t] = W1[t];
    if (tid < HH * 2 * DD) sa[tid] = a1[tid];
    __syncthreads();

    for (int t = tid; t < HH * NN; t += 256) {
        int hd = t >> 7, n = t & 127;
        float acc[8];
        #pragma unroll
        for (int d = 0; d < 8; d++) acc[d] = 0.f;
        const float* w = sW + hd * (FF * DD);
        const float* x = sX + n * 17;
        #pragma unroll
        for (int f = 0; f < FF; f++) {
            float xv = x[f];
            #pragma unroll
            for (int d = 0; d < 8; d++) acc[d] = fmaf(xv, w[(f << 3) + d], acc[d]);
        }
        const float* av = sa + (hd << 4);
        float ei = 0.f, ej = 0.f;
        #pragma unroll
        for (int d = 0; d < 8; d++) { ei = fmaf(acc[d], av[d], ei); ej = fmaf(acc[d], av[8 + d], ej); }
        #pragma unroll
        for (int d = 0; d < 8; d++) sh[(t << 3) + d] = acc[d];
        sei[t] = ei; sej[t] = ej;
        sPj[t] = __expf(ej); sQj[t] = __expf(0.01f * ej);
    }
    __syncthreads();
    gat_attention(sh, sei, sej, sPj, sQj, smask, sy, tid);
    __syncthreads();
    ln2d_apply(sy, g1, b1, sred, tid, nullptr, nullptr);
    __syncthreads();

    for (int t = tid; t < HH * GG * DD; t += 256) sW[t] = W2[t];
    if (tid < HH * 2 * DD) sa[tid] = a2[tid];
    __syncthreads();

    for (int t = tid; t < HH * NN; t += 256) {
        int hd = t >> 7, n = t & 127;
        float acc[8];
        #pragma unroll
        for (int d = 0; d < 8; d++) acc[d] = 0.f;
        const float* w = sW + hd * (GG * DD);
        const float* x = sy + n * 49;
        #pragma unroll
        for (int f = 0; f < GG; f++) {
            float xv = x[f];
            #pragma unroll
            for (int d = 0; d < 8; d++) acc[d] = fmaf(xv, w[(f << 3) + d], acc[d]);
        }
        const float* av = sa + (hd << 4);
        float ei = 0.f, ej = 0.f;
        #pragma unroll
        for (int d = 0; d < 8; d++) { ei = fmaf(acc[d], av[d], ei); ej = fmaf(acc[d], av[8 + d], ej); }
        #pragma unroll
        for (int d = 0; d < 8; d++) sh[(t << 3) + d] = acc[d];
        sei[t] = ei; sej[t] = ej;
        sPj[t] = __expf(ej); sQj[t] = __expf(0.01f * ej);
    }
    __syncthreads();
    gat_attention(sh, sei, sej, sPj, sQj, smask, sy, tid);
    __syncthreads();

    for (int t = tid; t < FF * GG; t += 256) sW[t] = Wr[t];
    if (tid < GG) sa[tid] = br[tid];
    __syncthreads();
    for (int t = tid; t < XG; t += 256) {
        int n = t / 48, c = t - n * 48;
        float accv = sa[c];
        const float* x = sX + n * 17;
        #pragma unroll
        for (int f = 0; f < FF; f++) accv = fmaf(x[f], sW[f * 48 + c], accv);
        sy[n * 49 + c] += accv;
    }
    __syncthreads();
    ln2d_apply(sy, g2, b2, sred, tid,
               g_xhi + (size_t)b * XG, g_xlo + (size_t)b * XG);
}

// =======================================================================
// Weight / activation split into tf32 hi/lo, canonical [Nn, Kk] layout.
// Element (n,k) read from W[n*ldn + k*ldk].
// =======================================================================
__global__ __launch_bounds__(256)
void wsplit(const float* __restrict__ W, uint32_t* __restrict__ hi,
            uint32_t* __restrict__ lo, int total, int Kk, int ldn, int ldk)
{
    int idx = blockIdx.x * 256 + threadIdx.x;
    if (idx >= total) return;
    int n = idx / Kk, k = idx - n * Kk;
    float v = W[(size_t)n * ldn + (size_t)k * ldk];
    tf32split(v, hi[idx], lo[idx]);
}

// =======================================================================
// 3xTF32 tensor-core GEMM: C[M,N] = A[M,K] @ B[N,K]^T (+bias, relu, split)
// BM=BN=64, BK=32, 128 threads = 4 warps (2x2), warp tile 32x32.
// All dims must be multiples of the tile (true for every call here).
// =======================================================================
__global__ __launch_bounds__(128)
void gemm_tf32(const uint32_t* __restrict__ Ahi, const uint32_t* __restrict__ Alo,
               const uint32_t* __restrict__ Bhi, const uint32_t* __restrict__ Blo,
               const float* __restrict__ bias, float* __restrict__ C,
               uint32_t* __restrict__ Chi, uint32_t* __restrict__ Clo,
               int M, int N, int K, int act)
{
    __shared__ uint32_t sA[2][64][36];   // [ver][m][k], pad 36 -> conflict-free frags
    __shared__ uint32_t sB[2][64][36];   // [ver][n][k]

    int tid  = threadIdx.x;
    int lane = tid & 31, wid = tid >> 5;
    int warpM = (wid >> 1) << 5;         // 0 / 32
    int warpN = (wid & 1) << 5;          // 0 / 32
    int g = lane >> 2, tig = lane & 3;
    int bm = blockIdx.y << 6, bn = blockIdx.x << 6;

    int lr = tid >> 3;                   // 0..15  (row)
    int lv = (tid & 7) << 2;             // 0..28  (k of float4)

    float acc[2][4][4];
    #pragma unroll
    for (int ms = 0; ms < 2; ms++)
        #pragma unroll
        for (int ns = 0; ns < 4; ns++)
            #pragma unroll
            for (int r = 0; r < 4; r++) acc[ms][ns][r] = 0.f;

    uint4 pAh[4], pAl[4], pBh[4], pBl[4];
    #pragma unroll
    for (int q = 0; q < 4; q++) {
        int row = lr + (q << 4);
        pAh[q] = *(const uint4*)(Ahi + (size_t)(bm + row) * K + lv);
        pAl[q] = *(const uint4*)(Alo + (size_t)(bm + row) * K + lv);
        pBh[q] = *(const uint4*)(Bhi + (size_t)(bn + row) * K + lv);
        pBl[q] = *(const uint4*)(Blo + (size_t)(bn + row) * K + lv);
    }

    for (int kt = 0; kt < K; kt += 32) {
        #pragma unroll
        for (int q = 0; q < 4; q++) {
            int row = lr + (q << 4);
            *(uint4*)&sA[0][row][lv] = pAh[q];
            *(uint4*)&sA[1][row][lv] = pAl[q];
            *(uint4*)&sB[0][row][lv] = pBh[q];
            *(uint4*)&sB[1][row][lv] = pBl[q];
        }
        __syncthreads();

        int ktn = kt + 32;
        if (ktn < K) {
            #pragma unroll
            for (int q = 0; q < 4; q++) {
                int row = lr + (q << 4);
                pAh[q] = *(const uint4*)(Ahi + (size_t)(bm + row) * K + ktn + lv);
                pAl[q] = *(const uint4*)(Alo + (size_t)(bm + row) * K + ktn + lv);
                pBh[q] = *(const uint4*)(Bhi + (size_t)(bn + row) * K + ktn + lv);
                pBl[q] = *(const uint4*)(Blo + (size_t)(bn + row) * K + ktn + lv);
            }
        }

        #pragma unroll
        for (int ks = 0; ks < 4; ks++) {
            int kk = ks << 3;
            uint32_t ah[2][4], al[2][4], bh[4][2], bl[4][2];
            #pragma unroll
            for (int ms = 0; ms < 2; ms++) {
                int mr = warpM + (ms << 4);
                ah[ms][0] = sA[0][mr + g    ][kk + tig];
                ah[ms][1] = sA[0][mr + g + 8][kk + tig];
                ah[ms][2] = sA[0][mr + g    ][kk + tig + 4];
                ah[ms][3] = sA[0][mr + g + 8][kk + tig + 4];
                al[ms][0] = sA[1][mr + g    ][kk + tig];
                al[ms][1] = sA[1][mr + g + 8][kk + tig];
                al[ms][2] = sA[1][mr + g    ][kk + tig + 4];
                al[ms][3] = sA[1][mr + g + 8][kk + tig + 4];
            }
            #pragma unroll
            for (int ns = 0; ns < 4; ns++) {
                int nc = warpN + (ns << 3);
                bh[ns][0] = sB[0][nc + g][kk + tig];
                bh[ns][1] = sB[0][nc + g][kk + tig + 4];
                bl[ns][0] = sB[1][nc + g][kk + tig];
                bl[ns][1] = sB[1][nc + g][kk + tig + 4];
            }
            #pragma unroll
            for (int ms = 0; ms < 2; ms++)
                #pragma unroll
                for (int ns = 0; ns < 4; ns++) {
                    mma_tf32(acc[ms][ns], ah[ms], bh[ns]);
                    mma_tf32(acc[ms][ns], ah[ms], bl[ns]);
                    mma_tf32(acc[ms][ns], al[ms], bh[ns]);
                }
        }
        __syncthreads();
    }

    #pragma unroll
    for (int ms = 0; ms < 2; ms++) {
        int r0 = bm + warpM + (ms << 4) + g;
        #pragma unroll
        for (int ns = 0; ns < 4; ns++) {
            int c0 = bn + warpN + (ns << 3) + (tig << 1);
            float b0v = bias ? bias[c0] : 0.f;
            float b1v = bias ? bias[c0 + 1] : 0.f;
            float v0 = acc[ms][ns][0] + b0v, v1 = acc[ms][ns][1] + b1v;
            float v2 = acc[ms][ns][2] + b0v, v3 = acc[ms][ns][3] + b1v;
            if (act) {
                v0 = fmaxf(v0, 0.f); v1 = fmaxf(v1, 0.f);
                v2 = fmaxf(v2, 0.f); v3 = fmaxf(v3, 0.f);
            }
            size_t o0 = (size_t)r0 * N + c0, o2 = (size_t)(r0 + 8) * N + c0;
            C[o0] = v0; C[o0 + 1] = v1; C[o2] = v2; C[o2 + 1] = v3;
            if (Chi) {
                tf32split(v0, Chi[o0],     Clo[o0]);
                tf32split(v1, Chi[o0 + 1], Clo[o0 + 1]);
                tf32split(v2, Chi[o2],     Clo[o2]);
                tf32split(v3, Chi[o2 + 1], Clo[o2 + 1]);
            }
        }
    }
}

// =======================================================================
// GRU gates with hidden == 0:  h = (1 - z) * n ; also emit tf32 splits
// =======================================================================
__global__ __launch_bounds__(256)
void gru_gates(const float* __restrict__ gi, const float* __restrict__ bhh,
               float* __restrict__ h, uint32_t* __restrict__ hhi,
               uint32_t* __restrict__ hlo)
{
    int idx = blockIdx.x * 256 + threadIdx.x;
    int b = idx >> 8, j = idx & 255;
    const float* g = gi + (size_t)b * G3;
    float r = 1.f / (1.f + __expf(-(g[j]       + bhh[j])));
    float z = 1.f / (1.f + __expf(-(g[256 + j] + bhh[256 + j])));
    float n = tanhf(g[512 + j] + r * bhh[512 + j]);
    float hv = (1.f - z) * n;
    h[idx] = hv;
    tf32split(hv, hhi[idx], hlo[idx]);
}

// =======================================================================
// LayerNorm over GRU dim, emits tf32 splits only
// =======================================================================
__global__ __launch_bounds__(256)
void ln1d_k(const float* __restrict__ h, const float* __restrict__ g,
            const float* __restrict__ b, uint32_t* __restrict__ ohi,
            uint32_t* __restrict__ olo)
{
    __shared__ float s1[8], s2[8], mv[2];
    int row = blockIdx.x, tid = threadIdx.x;
    float v = h[(size_t)row * GRUU + tid];
    float s = v, q = v * v;
    #pragma unroll
    for (int off = 16; off; off >>= 1) {
        s += __shfl_xor_sync(0xffffffffu, s, off);
        q += __shfl_xor_sync(0xffffffffu, q, off);
    }
    if ((tid & 31) == 0) { s1[tid >> 5] = s; s2[tid >> 5] = q; }
    __syncthreads();
    if (tid == 0) {
        float S = 0.f, Q = 0.f;
        #pragma unroll
        for (int i = 0; i < 8; i++) { S += s1[i]; Q += s2[i]; }
        float m = S * (1.f / 256.f);
        float var = Q * (1.f / 256.f) - m * m;
        mv[0] = m; mv[1] = rsqrtf(var + 1e-5f);
    }
    __syncthreads();
    float o = (v - mv[0]) * mv[1] * g[tid] + b[tid];
    tf32split(o, ohi[(size_t)row * GRUU + tid], olo[(size_t)row * GRUU + tid]);
}

// =======================================================================
// host launcher
// =======================================================================
extern "C" void kernel_launch(void* const* d_in, const int* in_sizes, int n_in,
                              void* d_out, int out_size)
{
    const float* X    = (const float*)d_in[0];
    const int*   A    = (const int*)  d_in[1];
    const float* W1   = (const float*)d_in[2];
    const float* a1   = (const float*)d_in[3];
    const float* W2   = (const float*)d_in[4];
    const float* a2   = (const float*)d_in[5];
    const float* Wr   = (const float*)d_in[6];
    const float* br   = (const float*)d_in[7];
    const float* g1   = (const float*)d_in[8];
    const float* b1   = (const float*)d_in[9];
    const float* g2   = (const float*)d_in[10];
    const float* b2   = (const float*)d_in[11];
    const float* Wih0 = (const float*)d_in[12];
    const float* bih0 = (const float*)d_in[14];
    const float* bhh0 = (const float*)d_in[15];
    const float* Wih1 = (const float*)d_in[16];
    const float* bih1 = (const float*)d_in[18];
    const float* bhh1 = (const float*)d_in[19];
    const float* Wih2 = (const float*)d_in[20];
    const float* bih2 = (const float*)d_in[22];
    const float* bhh2 = (const float*)d_in[23];
    const float* gng  = (const float*)d_in[24];
    const float* gnb  = (const float*)d_in[25];
    const float* We   = (const float*)d_in[26];
    const float* be   = (const float*)d_in[27];
    const float* Wp   = (const float*)d_in[28];
    const float* bp   = (const float*)d_in[29];
    float* out = (float*)d_out;

    uint32_t *pxhi, *pxlo, *pwhi, *pwlo, *phhi, *phlo, *plnhi, *plnlo, *pehi, *pelo;
    float *pgi, *ph, *pemb;
    cudaGetSymbolAddress((void**)&pxhi,  g_xhi);
    cudaGetSymbolAddress((void**)&pxlo,  g_xlo);
    cudaGetSymbolAddress((void**)&pwhi,  g_whi);
    cudaGetSymbolAddress((void**)&pwlo,  g_wlo);
    cudaGetSymbolAddress((void**)&pgi,   g_gi);
    cudaGetSymbolAddress((void**)&ph,    g_h);
    cudaGetSymbolAddress((void**)&phhi,  g_hhi);
    cudaGetSymbolAddress((void**)&phlo,  g_hlo);
    cudaGetSymbolAddress((void**)&plnhi, g_lnhi);
    cudaGetSymbolAddress((void**)&plnlo, g_lnlo);
    cudaGetSymbolAddress((void**)&pehi,  g_ehi);
    cudaGetSymbolAddress((void**)&pelo,  g_elo);
    cudaGetSymbolAddress((void**)&pemb,  g_emb);

    const int GAT_SMEM = (2176 + 6144 + 6272 + 4 * 768 + 2304 + 96 + 20 + 512) * 4;
    cudaFuncSetAttribute(gat_kernel, cudaFuncAttributeMaxDynamicSharedMemorySize, GAT_SMEM);

    // GAT -> g_xhi/g_xlo
    gat_kernel<<<BB, 256, GAT_SMEM>>>(X, A, W1, a1, W2, a2, Wr, br, g1, b1, g2, b2);

    dim3 gGru(G3 / 64, BB / 64);    // 12 x 16 = 192 CTAs

    // GRU layer 0: K = 6144
    wsplit<<<(G3 * XG + 255) / 256, 256>>>(Wih0, pwhi, pwlo, G3 * XG, XG, XG, 1);
    gemm_tf32<<<gGru, 128>>>(pxhi, pxlo, pwhi, pwlo, bih0, pgi, nullptr, nullptr,
                             BB, G3, XG, 0);
    gru_gates<<<BB, 256>>>(pgi, bhh0, ph, phhi, phlo);

    // GRU layer 1: K = 256
    wsplit<<<(G3 * GRUU + 255) / 256, 256>>>(Wih1, pwhi, pwlo, G3 * GRUU, GRUU, GRUU, 1);
    gemm_tf32<<<gGru, 128>>>(phhi, phlo, pwhi, pwlo, bih1, pgi, nullptr, nullptr,
                             BB, G3, GRUU, 0);
    gru_gates<<<BB, 256>>>(pgi, bhh1, ph, phhi, phlo);

    // GRU layer 2
    wsplit<<<(G3 * GRUU + 255) / 256, 256>>>(Wih2, pwhi, pwlo, G3 * GRUU, GRUU, GRUU, 1);
    gemm_tf32<<<gGru, 128>>>(phhi, phlo, pwhi, pwlo, bih2, pgi, nullptr, nullptr,
                             BB, G3, GRUU, 0);
    gru_gates<<<BB, 256>>>(pgi, bhh2, ph, phhi, phlo);

    // LayerNorm
    ln1d_k<<<BB, 256>>>(ph, gng, gnb, plnhi, plnlo);

    // emb = relu(hln @ We + be); We is [K=256, N=128] -> B(n,k)=We[k*128+n]
    float* embp = (out_size >= 2 * BB * EMBB) ? (out + (size_t)BB * EMBB) : pemb;
    wsplit<<<(EMBB * GRUU + 255) / 256, 256>>>(We, pwhi, pwlo, EMBB * GRUU, GRUU, 1, EMBB);
    dim3 gEmb(EMBB / 64, BB / 64);
    gemm_tf32<<<gEmb, 128>>>(plnhi, plnlo, pwhi, pwlo, be, embp, pehi, pelo,
                             BB, EMBB, GRUU, 1);

    // pred = emb @ Wp + bp; Wp is [K=128, N=128] -> B(n,k)=Wp[k*128+n]
    wsplit<<<(NN * EMBB + 255) / 256, 256>>>(Wp, pwhi, pwlo, NN * EMBB, EMBB, 1, NN);
    dim3 gPred(NN / 64, BB / 64);
    gemm_tf32<<<gPred, 128>>>(pehi, pelo, pwhi, pwlo, bp, out, nullptr, nullptr,
                              BB, NN, EMBB, 0);
}

// round 4
// speedup vs baseline: 1.6297x; 1.1359x over previous
#include <cuda_runtime.h>
#include <cstdint>

// ---------------- problem constants ----------------
#define BB   1024
#define NN   128
#define FF   16
#define GG   48
#define HH   6
#define DD   8
#define GRUU 256
#define EMBB 128
#define XG   (NN*GG)       // 6144
#define G3   (3*GRUU)      // 768

// ---------------- scratch ----------------
__device__ float g_x  [BB*XG];
__device__ float g_gi [BB*G3];
__device__ float g_h  [BB*GRUU];
__device__ float g_hln[BB*GRUU];
__device__ float g_emb[BB*EMBB];

// ---------------- helpers ----------------
__device__ __forceinline__ void tf32split(float v, uint32_t& h, uint32_t& l) {
    uint32_t hb; asm("cvt.rna.tf32.f32 %0, %1;" : "=r"(hb) : "f"(v));
    float lv = v - __uint_as_float(hb);
    uint32_t lb; asm("cvt.rna.tf32.f32 %0, %1;" : "=r"(lb) : "f"(lv));
    h = hb; l = lb;
}

__device__ __forceinline__ uint32_t smem_u32(const void* p) {
    uint32_t a;
    asm("{ .reg .u64 t; cvta.to.shared.u64 t, %1; cvt.u32.u64 %0, t; }" : "=r"(a) : "l"(p));
    return a;
}

__device__ __forceinline__ void ldsm_x4(uint32_t* d, uint32_t addr) {
    asm volatile("ldmatrix.sync.aligned.m8n8.x4.shared.b16 {%0,%1,%2,%3}, [%4];"
        : "=r"(d[0]), "=r"(d[1]), "=r"(d[2]), "=r"(d[3]) : "r"(addr));
}

__device__ __forceinline__ void mma_tf32(float* c, const uint32_t* a, const uint32_t* b) {
    asm volatile("mma.sync.aligned.m16n8k8.row.col.f32.tf32.tf32.f32 "
        "{%0,%1,%2,%3}, {%4,%5,%6,%7}, {%8,%9}, {%0,%1,%2,%3};\n"
        : "+f"(c[0]), "+f"(c[1]), "+f"(c[2]), "+f"(c[3])
        : "r"(a[0]), "r"(a[1]), "r"(a[2]), "r"(a[3]), "r"(b[0]), "r"(b[1]));
}

// =======================================================================
// GAT kernel (rank-1 exp trick; plain-float output)
// =======================================================================
__device__ __forceinline__ void gat_attention(
    const float* __restrict__ sh, const float* __restrict__ sei,
    const float* __restrict__ sej, const float* __restrict__ sPj,
    const float* __restrict__ sQj, const unsigned* __restrict__ smask,
    float* __restrict__ sy, int tid)
{
    #pragma unroll 1
    for (int rep = 0; rep < 3; rep++) {
        int r  = rep * 256 + tid;
        int hd = r >> 7, i = r & 127;
        float eiv = sei[r];
        float Pi = __expf(eiv), Qi = __expf(0.01f * eiv);
        float acc[8];
        #pragma unroll
        for (int d = 0; d < 8; d++) acc[d] = 0.f;
        float ssum = 0.f;
        const unsigned* mrow = smask + (i << 2);
        const float* ejp = sej + (hd << 7);
        const float* Pjp = sPj + (hd << 7);
        const float* Qjp = sQj + (hd << 7);
        const float* hp  = sh  + (hd << 10);
        #pragma unroll 1
        for (int jw = 0; jw < 4; jw++) {
            unsigned bits = mrow[jw];
            #pragma unroll
            for (int jq = 0; jq < 8; jq++) {
                int j0 = (jw << 5) + (jq << 2);
                float4 e4 = *(const float4*)(ejp + j0);
                float4 P4 = *(const float4*)(Pjp + j0);
                float4 Q4 = *(const float4*)(Qjp + j0);
                float ee[4] = {e4.x, e4.y, e4.z, e4.w};
                float PP[4] = {P4.x, P4.y, P4.z, P4.w};
                float QQ[4] = {Q4.x, Q4.y, Q4.z, Q4.w};
                #pragma unroll
                for (int t = 0; t < 4; t++) {
                    int j = j0 + t;
                    float w = (eiv + ee[t] > 0.f) ? (Pi * PP[t]) : (Qi * QQ[t]);
                    w = (bits & (1u << ((jq << 2) + t))) ? w : 0.f;
                    ssum += w;
                    float4 h0 = *(const float4*)(hp + (j << 3));
                    float4 h1 = *(const float4*)(hp + (j << 3) + 4);
                    acc[0] = fmaf(w, h0.x, acc[0]); acc[1] = fmaf(w, h0.y, acc[1]);
                    acc[2] = fmaf(w, h0.z, acc[2]); acc[3] = fmaf(w, h0.w, acc[3]);
                    acc[4] = fmaf(w, h1.x, acc[4]); acc[5] = fmaf(w, h1.y, acc[5]);
                    acc[6] = fmaf(w, h1.z, acc[6]); acc[7] = fmaf(w, h1.w, acc[7]);
                }
            }
        }
        float inv = 1.0f / ssum;
        float* o = sy + i * 49 + (hd << 3);
        #pragma unroll
        for (int d = 0; d < 8; d++) o[d] = acc[d] * inv;
    }
}

__device__ __forceinline__ void ln2d_apply(
    float* __restrict__ sy, const float* __restrict__ gamma,
    const float* __restrict__ beta, float* __restrict__ sred,
    int tid, float* __restrict__ gout)
{
    float s = 0.f, q = 0.f;
    for (int t = tid; t < XG; t += 256) {
        int n = t / 48, c = t - n * 48;
        float v = sy[n * 49 + c];
        s += v; q += v * v;
    }
    #pragma unroll
    for (int o = 16; o; o >>= 1) {
        s += __shfl_xor_sync(0xffffffffu, s, o);
        q += __shfl_xor_sync(0xffffffffu, q, o);
    }
    int wid = tid >> 5;
    if ((tid & 31) == 0) { sred[wid] = s; sred[8 + wid] = q; }
    __syncthreads();
    if (tid == 0) {
        float S = 0.f, Q = 0.f;
        #pragma unroll
        for (int i = 0; i < 8; i++) { S += sred[i]; Q += sred[8 + i]; }
        float m   = S * (1.f / (float)XG);
        float var = Q * (1.f / (float)XG) - m * m;
        sred[16] = m;
        sred[17] = rsqrtf(var + 1e-5f);
    }
    __syncthreads();
    float m = sred[16], rs = sred[17];
    for (int t = tid; t < XG; t += 256) {
        int n = t / 48, c = t - n * 48;
        float v = (sy[n * 49 + c] - m) * rs * gamma[t] + beta[t];
        v = fmaxf(v, 0.f);
        if (gout) gout[t] = v; else sy[n * 49 + c] = v;
    }
}

__global__ __launch_bounds__(256)
void gat_kernel(const float* __restrict__ X,  const int* __restrict__ A,
                const float* __restrict__ W1, const float* __restrict__ a1,
                const float* __restrict__ W2, const float* __restrict__ a2,
                const float* __restrict__ Wr, const float* __restrict__ br,
                const float* __restrict__ g1, const float* __restrict__ b1,
                const float* __restrict__ g2, const float* __restrict__ b2)
{
    extern __shared__ float sm[];
    float*    sX    = sm;               // 2176
    float*    sh    = sX  + 2176;       // 6144
    float*    sy    = sh  + 6144;       // 6272
    float*    sei   = sy  + 6272;       // 768
    float*    sej   = sei + 768;        // 768
    float*    sPj   = sej + 768;        // 768
    float*    sQj   = sPj + 768;        // 768
    float*    sW    = sQj + 768;        // 2304
    float*    sa    = sW  + 2304;       // 96
    float*    sred  = sa  + 96;         // 20
    unsigned* smask = (unsigned*)(sred + 20); // 512

    int b = blockIdx.x, tid = threadIdx.x;

    const float* Xb = X + (size_t)b * (NN * FF);
    for (int t = tid; t < NN * FF; t += 256)
        sX[(t >> 4) * 17 + (t & 15)] = Xb[t];

    {
        const int* Ab = A + (size_t)b * (NN * NN);
        int lane = tid & 31, wid = tid >> 5;
        for (int w = wid; w < 512; w += 8) {
            int i = w >> 2, j0 = (w & 3) << 5;
            unsigned bits = __ballot_sync(0xffffffffu, Ab[(i << 7) + j0 + lane] != 0);
            if (lane == 0) smask[w] = bits;
        }
    }
    for (int t = tid; t < HH * FF * DD; t += 256) sW[t] = W1[t];
    if (tid < HH * 2 * DD) sa[tid] = a1[tid];
    __syncthreads();

    for (int t = tid; t < HH * NN; t += 256) {
        int hd = t >> 7, n = t & 127;
        float acc[8];
        #pragma unroll
        for (int d = 0; d < 8; d++) acc[d] = 0.f;
        const float* w = sW + hd * (FF * DD);
        const float* x = sX + n * 17;
        #pragma unroll
        for (int f = 0; f < FF; f++) {
            float xv = x[f];
            #pragma unroll
            for (int d = 0; d < 8; d++) acc[d] = fmaf(xv, w[(f << 3) + d], acc[d]);
        }
        const float* av = sa + (hd << 4);
        float ei = 0.f, ej = 0.f;
        #pragma unroll
        for (int d = 0; d < 8; d++) { ei = fmaf(acc[d], av[d], ei); ej = fmaf(acc[d], av[8 + d], ej); }
        #pragma unroll
        for (int d = 0; d < 8; d++) sh[(t << 3) + d] = acc[d];
        sei[t] = ei; sej[t] = ej;
        sPj[t] = __expf(ej); sQj[t] = __expf(0.01f * ej);
    }
    __syncthreads();
    gat_attention(sh, sei, sej, sPj, sQj, smask, sy, tid);
    __syncthreads();
    ln2d_apply(sy, g1, b1, sred, tid, nullptr);
    __syncthreads();

    for (int t = tid; t < HH * GG * DD; t += 256) sW[t] = W2[t];
    if (tid < HH * 2 * DD) sa[tid] = a2[tid];
    __syncthreads();

    for (int t = tid; t < HH * NN; t += 256) {
        int hd = t >> 7, n = t & 127;
        float acc[8];
        #pragma unroll
        for (int d = 0; d < 8; d++) acc[d] = 0.f;
        const float* w = sW + hd * (GG * DD);
        const float* x = sy + n * 49;
        #pragma unroll
        for (int f = 0; f < GG; f++) {
            float xv = x[f];
            #pragma unroll
            for (int d = 0; d < 8; d++) acc[d] = fmaf(xv, w[(f << 3) + d], acc[d]);
        }
        const float* av = sa + (hd << 4);
        float ei = 0.f, ej = 0.f;
        #pragma unroll
        for (int d = 0; d < 8; d++) { ei = fmaf(acc[d], av[d], ei); ej = fmaf(acc[d], av[8 + d], ej); }
        #pragma unroll
        for (int d = 0; d < 8; d++) sh[(t << 3) + d] = acc[d];
        sei[t] = ei; sej[t] = ej;
        sPj[t] = __expf(ej); sQj[t] = __expf(0.01f * ej);
    }
    __syncthreads();
    gat_attention(sh, sei, sej, sPj, sQj, smask, sy, tid);
    __syncthreads();

    for (int t = tid; t < FF * GG; t += 256) sW[t] = Wr[t];
    if (tid < GG) sa[tid] = br[tid];
    __syncthreads();
    for (int t = tid; t < XG; t += 256) {
        int n = t / 48, c = t - n * 48;
        float accv = sa[c];
        const float* x = sX + n * 17;
        #pragma unroll
        for (int f = 0; f < FF; f++) accv = fmaf(x[f], sW[f * 48 + c], accv);
        sy[n * 49 + c] += accv;
    }
    __syncthreads();
    ln2d_apply(sy, g2, b2, sred, tid, g_x + (size_t)b * XG);
}

// =======================================================================
// 3xTF32 tensor-core GEMM, fp32 in / fp32 out, in-kernel tf32 split.
// C[M,N] = A[M,K] @ B^T.  B element (n,k) at:
//   bTrans==0 : B[n*K + k]        (row-major [N,K])
//   bTrans==1 : B[k*ldb + n]      (row-major [K,N])
// BM=BN=64, BK=32, 256 threads = 8 warps (4x2), warp tile 16x32.
// Fragments via ldmatrix (b16-as-tf32 trick). Requires M%64==N%64==0, K%32==0.
// =======================================================================
__global__ __launch_bounds__(256)
void gemm_tf32(const float* __restrict__ Af, const float* __restrict__ Bf,
               const float* __restrict__ bias, float* __restrict__ C,
               int M, int N, int K, int ldb, int bTrans, int act)
{
    __shared__ uint32_t sA[2][64][36];   // [hi/lo][m][k]
    __shared__ uint32_t sB[2][64][36];   // [hi/lo][n][k]

    int tid  = threadIdx.x;
    int lane = tid & 31, wid = tid >> 5;
    int warpM = (wid >> 1) << 4;         // 0,16,32,48
    int warpN = (wid & 1) << 5;          // 0,32
    int g = lane >> 2, tig = lane & 3;
    int bm = blockIdx.y << 6, bn = blockIdx.x << 6;

    // ldmatrix per-lane base addresses (bytes)
    uint32_t aBase = smem_u32(&sA[0][0][0]) +
        (((warpM + (lane & 15)) * 36 + ((lane >> 4) << 2)) << 2);
    uint32_t bBase0 = smem_u32(&sB[0][0][0]) +
        (((warpN + ((lane >> 4) << 3) + (lane & 7)) * 36 + (((lane >> 3) & 1) << 2)) << 2);
    uint32_t bBase1 = bBase0 + (16 * 36 << 2);
    const uint32_t LO = (64 * 36) << 2;  // hi -> lo plane offset (bytes)

    float acc[4][4];
    #pragma unroll
    for (int ns = 0; ns < 4; ns++)
        #pragma unroll
        for (int r = 0; r < 4; r++) acc[ns][r] = 0.f;

    // prefetch first tiles
    float4 pA[2], pB[2];
    #pragma unroll
    for (int q = 0; q < 2; q++) {
        int idx = tid + (q << 8);
        if (!bTrans) {
            int row = idx >> 3, kc = (idx & 7) << 2;
            pA[q] = *(const float4*)(Af + (size_t)(bm + row) * K + kc);
            pB[q] = *(const float4*)(Bf + (size_t)(bn + row) * K + kc);
        } else {
            int row = idx >> 3, kc = (idx & 7) << 2;
            pA[q] = *(const float4*)(Af + (size_t)(bm + row) * K + kc);
            int k = idx >> 4, n0 = (idx & 15) << 2;
            pB[q] = *(const float4*)(Bf + (size_t)k * ldb + bn + n0);
        }
    }

    for (int kt = 0; kt < K; kt += 32) {
        // store with split
        #pragma unroll
        for (int q = 0; q < 2; q++) {
            int idx = tid + (q << 8);
            {
                int row = idx >> 3, kc = (idx & 7) << 2;
                uint4 hi, lo;
                tf32split(pA[q].x, hi.x, lo.x); tf32split(pA[q].y, hi.y, lo.y);
                tf32split(pA[q].z, hi.z, lo.z); tf32split(pA[q].w, hi.w, lo.w);
                *(uint4*)&sA[0][row][kc] = hi;
                *(uint4*)&sA[1][row][kc] = lo;
            }
            if (!bTrans) {
                int row = idx >> 3, kc = (idx & 7) << 2;
                uint4 hi, lo;
                tf32split(pB[q].x, hi.x, lo.x); tf32split(pB[q].y, hi.y, lo.y);
                tf32split(pB[q].z, hi.z, lo.z); tf32split(pB[q].w, hi.w, lo.w);
                *(uint4*)&sB[0][row][kc] = hi;
                *(uint4*)&sB[1][row][kc] = lo;
            } else {
                int k = idx >> 4, n0 = (idx & 15) << 2;
                float v[4] = {pB[q].x, pB[q].y, pB[q].z, pB[q].w};
                #pragma unroll
                for (int j = 0; j < 4; j++) {
                    uint32_t hb, lb; tf32split(v[j], hb, lb);
                    sB[0][n0 + j][k] = hb; sB[1][n0 + j][k] = lb;
                }
            }
        }
        __syncthreads();

        int ktn = kt + 32;
        if (ktn < K) {
            #pragma unroll
            for (int q = 0; q < 2; q++) {
                int idx = tid + (q << 8);
                int row = idx >> 3, kc = (idx & 7) << 2;
                pA[q] = *(const float4*)(Af + (size_t)(bm + row) * K + ktn + kc);
                if (!bTrans)
                    pB[q] = *(const float4*)(Bf + (size_t)(bn + row) * K + ktn + kc);
                else {
                    int k = idx >> 4, n0 = (idx & 15) << 2;
                    pB[q] = *(const float4*)(Bf + (size_t)(ktn + k) * ldb + bn + n0);
                }
            }
        }

        #pragma unroll
        for (int ks = 0; ks < 4; ks++) {
            uint32_t koff = (ks << 3) << 2;  // kk words -> bytes
            uint32_t ah[4], al[4], bh[2][4], bl[2][4];
            ldsm_x4(ah, aBase + koff);
            ldsm_x4(al, aBase + LO + koff);
            ldsm_x4(bh[0], bBase0 + koff);
            ldsm_x4(bl[0], bBase0 + LO + koff);
            ldsm_x4(bh[1], bBase1 + koff);
            ldsm_x4(bl[1], bBase1 + LO + koff);
            #pragma unroll
            for (int p = 0; p < 2; p++)
                #pragma unroll
                for (int half = 0; half < 2; half++) {
                    int ns = (p << 1) + half;
                    const uint32_t bfh[2] = {bh[p][half << 1], bh[p][(half << 1) + 1]};
                    const uint32_t bfl[2] = {bl[p][half << 1], bl[p][(half << 1) + 1]};
                    mma_tf32(acc[ns], ah, bfh);
                    mma_tf32(acc[ns], ah, bfl);
                    mma_tf32(acc[ns], al, bfh);
                }
        }
        __syncthreads();
    }

    int r0 = bm + warpM + g;
    #pragma unroll
    for (int ns = 0; ns < 4; ns++) {
        int c0 = bn + warpN + (ns << 3) + (tig << 1);
        float b0v = bias[c0], b1v = bias[c0 + 1];
        float v0 = acc[ns][0] + b0v, v1 = acc[ns][1] + b1v;
        float v2 = acc[ns][2] + b0v, v3 = acc[ns][3] + b1v;
        if (act) {
            v0 = fmaxf(v0, 0.f); v1 = fmaxf(v1, 0.f);
            v2 = fmaxf(v2, 0.f); v3 = fmaxf(v3, 0.f);
        }
        size_t o0 = (size_t)r0 * N + c0, o2 = (size_t)(r0 + 8) * N + c0;
        C[o0] = v0; C[o0 + 1] = v1; C[o2] = v2; C[o2 + 1] = v3;
    }
}

// =======================================================================
// GRU gates with hidden == 0:  h = (1 - z) * n
// =======================================================================
__global__ __launch_bounds__(256)
void gru_gates(const float* __restrict__ gi, const float* __restrict__ bhh,
               float* __restrict__ h)
{
    int idx = blockIdx.x * 256 + threadIdx.x;
    int b = idx >> 8, j = idx & 255;
    const float* g = gi + (size_t)b * G3;
    float r = 1.f / (1.f + __expf(-(g[j]       + bhh[j])));
    float z = 1.f / (1.f + __expf(-(g[256 + j] + bhh[256 + j])));
    float n = tanhf(g[512 + j] + r * bhh[512 + j]);
    h[idx] = (1.f - z) * n;
}

// =======================================================================
// LayerNorm over GRU dim
// =======================================================================
__global__ __launch_bounds__(256)
void ln1d_k(const float* __restrict__ h, const float* __restrict__ g,
            const float* __restrict__ b, float* __restrict__ o)
{
    __shared__ float s1[8], s2[8], mv[2];
    int row = blockIdx.x, tid = threadIdx.x;
    float v = h[(size_t)row * GRUU + tid];
    float s = v, q = v * v;
    #pragma unroll
    for (int off = 16; off; off >>= 1) {
        s += __shfl_xor_sync(0xffffffffu, s, off);
        q += __shfl_xor_sync(0xffffffffu, q, off);
    }
    if ((tid & 31) == 0) { s1[tid >> 5] = s; s2[tid >> 5] = q; }
    __syncthreads();
    if (tid == 0) {
        float S = 0.f, Q = 0.f;
        #pragma unroll
        for (int i = 0; i < 8; i++) { S += s1[i]; Q += s2[i]; }
        float m = S * (1.f / 256.f);
        float var = Q * (1.f / 256.f) - m * m;
        mv[0] = m; mv[1] = rsqrtf(var + 1e-5f);
    }
    __syncthreads();
    o[(size_t)row * GRUU + tid] = (v - mv[0]) * mv[1] * g[tid] + b[tid];
}

// =======================================================================
// host launcher
// =======================================================================
extern "C" void kernel_launch(void* const* d_in, const int* in_sizes, int n_in,
                              void* d_out, int out_size)
{
    const float* X    = (const float*)d_in[0];
    const int*   A    = (const int*)  d_in[1];
    const float* W1   = (const float*)d_in[2];
    const float* a1   = (const float*)d_in[3];
    const float* W2   = (const float*)d_in[4];
    const float* a2   = (const float*)d_in[5];
    const float* Wr   = (const float*)d_in[6];
    const float* br   = (const float*)d_in[7];
    const float* g1   = (const float*)d_in[8];
    const float* b1   = (const float*)d_in[9];
    const float* g2   = (const float*)d_in[10];
    const float* b2   = (const float*)d_in[11];
    const float* Wih0 = (const float*)d_in[12];
    const float* bih0 = (const float*)d_in[14];
    const float* bhh0 = (const float*)d_in[15];
    const float* Wih1 = (const float*)d_in[16];
    const float* bih1 = (const float*)d_in[18];
    const float* bhh1 = (const float*)d_in[19];
    const float* Wih2 = (const float*)d_in[20];
    const float* bih2 = (const float*)d_in[22];
    const float* bhh2 = (const float*)d_in[23];
    const float* gng  = (const float*)d_in[24];
    const float* gnb  = (const float*)d_in[25];
    const float* We   = (const float*)d_in[26];
    const float* be   = (const float*)d_in[27];
    const float* Wp   = (const float*)d_in[28];
    const float* bp   = (const float*)d_in[29];
    float* out = (float*)d_out;

    float *px, *pgi, *ph, *phln, *pemb;
    cudaGetSymbolAddress((void**)&px,   g_x);
    cudaGetSymbolAddress((void**)&pgi,  g_gi);
    cudaGetSymbolAddress((void**)&ph,   g_h);
    cudaGetSymbolAddress((void**)&phln, g_hln);
    cudaGetSymbolAddress((void**)&pemb, g_emb);

    const int GAT_SMEM = (2176 + 6144 + 6272 + 4 * 768 + 2304 + 96 + 20 + 512) * 4;
    cudaFuncSetAttribute(gat_kernel, cudaFuncAttributeMaxDynamicSharedMemorySize, GAT_SMEM);

    gat_kernel<<<BB, 256, GAT_SMEM>>>(X, A, W1, a1, W2, a2, Wr, br, g1, b1, g2, b2);

    dim3 gGru(G3 / 64, BB / 64);   // 12 x 16

    gemm_tf32<<<gGru, 256>>>(px, Wih0, bih0, pgi, BB, G3, XG,   0, 0, 0);
    gru_gates<<<BB, 256>>>(pgi, bhh0, ph);
    gemm_tf32<<<gGru, 256>>>(ph, Wih1, bih1, pgi, BB, G3, GRUU, 0, 0, 0);
    gru_gates<<<BB, 256>>>(pgi, bhh1, ph);
    gemm_tf32<<<gGru, 256>>>(ph, Wih2, bih2, pgi, BB, G3, GRUU, 0, 0, 0);
    gru_gates<<<BB, 256>>>(pgi, bhh2, ph);

    ln1d_k<<<BB, 256>>>(ph, gng, gnb, phln);

    float* embp = (out_size >= 2 * BB * EMBB) ? (out + (size_t)BB * EMBB) : pemb;
    dim3 gEmb(EMBB / 64, BB / 64);
    // emb = relu(hln @ We + be); We is [K=256, N=128] row-major -> bTrans, ldb=EMBB
    gemm_tf32<<<gEmb, 256>>>(phln, We, be, embp, BB, EMBB, GRUU, EMBB, 1, 1);

    dim3 gPred(NN / 64, BB / 64);
    // pred = emb @ Wp + bp; Wp is [K=128, N=128] row-major -> bTrans, ldb=NN
    gemm_tf32<<<gPred, 256>>>(embp, Wp, bp, out, BB, NN, EMBB, NN, 1, 0);
}

// round 5
// speedup vs baseline: 1.7788x; 1.0915x over previous
#include <cuda_runtime.h>
#include <cstdint>

// ---------------- problem constants ----------------
#define BB   1024
#define NN   128
#define FF   16
#define GG   48
#define HH   6
#define DD   8
#define GRUU 256
#define EMBB 128
#define XG   (NN*GG)       // 6144
#define G3   (3*GRUU)      // 768
#define SPLITK 4

// ---------------- scratch ----------------
__device__ float g_x  [BB*XG];
__device__ float g_gip[SPLITK*BB*G3];   // split-K partials (also reused as gi for S=1)
__device__ float g_h  [BB*GRUU];
__device__ float g_hln[BB*GRUU];
__device__ float g_emb[BB*EMBB];

// ---------------- helpers ----------------
__device__ __forceinline__ void tf32split(float v, uint32_t& h, uint32_t& l) {
    uint32_t hb; asm("cvt.rna.tf32.f32 %0, %1;" : "=r"(hb) : "f"(v));
    float lv = v - __uint_as_float(hb);
    uint32_t lb; asm("cvt.rna.tf32.f32 %0, %1;" : "=r"(lb) : "f"(lv));
    h = hb; l = lb;
}

__device__ __forceinline__ uint32_t smem_u32(const void* p) {
    uint32_t a;
    asm("{ .reg .u64 t; cvta.to.shared.u64 t, %1; cvt.u32.u64 %0, t; }" : "=r"(a) : "l"(p));
    return a;
}

__device__ __forceinline__ void ldsm_x4(uint32_t* d, uint32_t addr) {
    asm volatile("ldmatrix.sync.aligned.m8n8.x4.shared.b16 {%0,%1,%2,%3}, [%4];"
        : "=r"(d[0]), "=r"(d[1]), "=r"(d[2]), "=r"(d[3]) : "r"(addr));
}

__device__ __forceinline__ void mma_tf32(float* c, const uint32_t* a, const uint32_t* b) {
    asm volatile("mma.sync.aligned.m16n8k8.row.col.f32.tf32.tf32.f32 "
        "{%0,%1,%2,%3}, {%4,%5,%6,%7}, {%8,%9}, {%0,%1,%2,%3};\n"
        : "+f"(c[0]), "+f"(c[1]), "+f"(c[2]), "+f"(c[3])
        : "r"(a[0]), "r"(a[1]), "r"(a[2]), "r"(a[3]), "r"(b[0]), "r"(b[1]));
}

// =======================================================================
// GAT kernel (rank-1 exp trick; unchanged from R4)
// =======================================================================
__device__ __forceinline__ void gat_attention(
    const float* __restrict__ sh, const float* __restrict__ sei,
    const float* __restrict__ sej, const float* __restrict__ sPj,
    const float* __restrict__ sQj, const unsigned* __restrict__ smask,
    float* __restrict__ sy, int tid)
{
    #pragma unroll 1
    for (int rep = 0; rep < 3; rep++) {
        int r  = rep * 256 + tid;
        int hd = r >> 7, i = r & 127;
        float eiv = sei[r];
        float Pi = __expf(eiv), Qi = __expf(0.01f * eiv);
        float acc[8];
        #pragma unroll
        for (int d = 0; d < 8; d++) acc[d] = 0.f;
        float ssum = 0.f;
        const unsigned* mrow = smask + (i << 2);
        const float* ejp = sej + (hd << 7);
        const float* Pjp = sPj + (hd << 7);
        const float* Qjp = sQj + (hd << 7);
        const float* hp  = sh  + (hd << 10);
        #pragma unroll 1
        for (int jw = 0; jw < 4; jw++) {
            unsigned bits = mrow[jw];
            #pragma unroll
            for (int jq = 0; jq < 8; jq++) {
                int j0 = (jw << 5) + (jq << 2);
                float4 e4 = *(const float4*)(ejp + j0);
                float4 P4 = *(const float4*)(Pjp + j0);
                float4 Q4 = *(const float4*)(Qjp + j0);
                float ee[4] = {e4.x, e4.y, e4.z, e4.w};
                float PP[4] = {P4.x, P4.y, P4.z, P4.w};
                float QQ[4] = {Q4.x, Q4.y, Q4.z, Q4.w};
                #pragma unroll
                for (int t = 0; t < 4; t++) {
                    int j = j0 + t;
                    float w = (eiv + ee[t] > 0.f) ? (Pi * PP[t]) : (Qi * QQ[t]);
                    w = (bits & (1u << ((jq << 2) + t))) ? w : 0.f;
                    ssum += w;
                    float4 h0 = *(const float4*)(hp + (j << 3));
                    float4 h1 = *(const float4*)(hp + (j << 3) + 4);
                    acc[0] = fmaf(w, h0.x, acc[0]); acc[1] = fmaf(w, h0.y, acc[1]);
                    acc[2] = fmaf(w, h0.z, acc[2]); acc[3] = fmaf(w, h0.w, acc[3]);
                    acc[4] = fmaf(w, h1.x, acc[4]); acc[5] = fmaf(w, h1.y, acc[5]);
                    acc[6] = fmaf(w, h1.z, acc[6]); acc[7] = fmaf(w, h1.w, acc[7]);
                }
            }
        }
        float inv = 1.0f / ssum;
        float* o = sy + i * 49 + (hd << 3);
        #pragma unroll
        for (int d = 0; d < 8; d++) o[d] = acc[d] * inv;
    }
}

__device__ __forceinline__ void ln2d_apply(
    float* __restrict__ sy, const float* __restrict__ gamma,
    const float* __restrict__ beta, float* __restrict__ sred,
    int tid, float* __restrict__ gout)
{
    float s = 0.f, q = 0.f;
    for (int t = tid; t < XG; t += 256) {
        int n = t / 48, c = t - n * 48;
        float v = sy[n * 49 + c];
        s += v; q += v * v;
    }
    #pragma unroll
    for (int o = 16; o; o >>= 1) {
        s += __shfl_xor_sync(0xffffffffu, s, o);
        q += __shfl_xor_sync(0xffffffffu, q, o);
    }
    int wid = tid >> 5;
    if ((tid & 31) == 0) { sred[wid] = s; sred[8 + wid] = q; }
    __syncthreads();
    if (tid == 0) {
        float S = 0.f, Q = 0.f;
        #pragma unroll
        for (int i = 0; i < 8; i++) { S += sred[i]; Q += sred[8 + i]; }
        float m   = S * (1.f / (float)XG);
        float var = Q * (1.f / (float)XG) - m * m;
        sred[16] = m;
        sred[17] = rsqrtf(var + 1e-5f);
    }
    __syncthreads();
    float m = sred[16], rs = sred[17];
    for (int t = tid; t < XG; t += 256) {
        int n = t / 48, c = t - n * 48;
        float v = (sy[n * 49 + c] - m) * rs * gamma[t] + beta[t];
        v = fmaxf(v, 0.f);
        if (gout) gout[t] = v; else sy[n * 49 + c] = v;
    }
}

__global__ __launch_bounds__(256)
void gat_kernel(const float* __restrict__ X,  const int* __restrict__ A,
                const float* __restrict__ W1, const float* __restrict__ a1,
                const float* __restrict__ W2, const float* __restrict__ a2,
                const float* __restrict__ Wr, const float* __restrict__ br,
                const float* __restrict__ g1, const float* __restrict__ b1,
                const float* __restrict__ g2, const float* __restrict__ b2)
{
    extern __shared__ float sm[];
    float*    sX    = sm;               // 2176
    float*    sh    = sX  + 2176;       // 6144
    float*    sy    = sh  + 6144;       // 6272
    float*    sei   = sy  + 6272;       // 768
    float*    sej   = sei + 768;        // 768
    float*    sPj   = sej + 768;        // 768
    float*    sQj   = sPj + 768;        // 768
    float*    sW    = sQj + 768;        // 2304
    float*    sa    = sW  + 2304;       // 96
    float*    sred  = sa  + 96;         // 20
    unsigned* smask = (unsigned*)(sred + 20); // 512

    int b = blockIdx.x, tid = threadIdx.x;

    const float* Xb = X + (size_t)b * (NN * FF);
    for (int t = tid; t < NN * FF; t += 256)
        sX[(t >> 4) * 17 + (t & 15)] = Xb[t];

    {
        const int* Ab = A + (size_t)b * (NN * NN);
        int lane = tid & 31, wid = tid >> 5;
        for (int w = wid; w < 512; w += 8) {
            int i = w >> 2, j0 = (w & 3) << 5;
            unsigned bits = __ballot_sync(0xffffffffu, Ab[(i << 7) + j0 + lane] != 0);
            if (lane == 0) smask[w] = bits;
        }
    }
    for (int t = tid; t < HH * FF * DD; t += 256) sW[t] = W1[t];
    if (tid < HH * 2 * DD) sa[tid] = a1[tid];
    __syncthreads();

    for (int t = tid; t < HH * NN; t += 256) {
        int hd = t >> 7, n = t & 127;
        float acc[8];
        #pragma unroll
        for (int d = 0; d < 8; d++) acc[d] = 0.f;
        const float* w = sW + hd * (FF * DD);
        const float* x = sX + n * 17;
        #pragma unroll
        for (int f = 0; f < FF; f++) {
            float xv = x[f];
            #pragma unroll
            for (int d = 0; d < 8; d++) acc[d] = fmaf(xv, w[(f << 3) + d], acc[d]);
        }
        const float* av = sa + (hd << 4);
        float ei = 0.f, ej = 0.f;
        #pragma unroll
        for (int d = 0; d < 8; d++) { ei = fmaf(acc[d], av[d], ei); ej = fmaf(acc[d], av[8 + d], ej); }
        #pragma unroll
        for (int d = 0; d < 8; d++) sh[(t << 3) + d] = acc[d];
        sei[t] = ei; sej[t] = ej;
        sPj[t] = __expf(ej); sQj[t] = __expf(0.01f * ej);
    }
    __syncthreads();
    gat_attention(sh, sei, sej, sPj, sQj, smask, sy, tid);
    __syncthreads();
    ln2d_apply(sy, g1, b1, sred, tid, nullptr);
    __syncthreads();

    for (int t = tid; t < HH * GG * DD; t += 256) sW[t] = W2[t];
    if (tid < HH * 2 * DD) sa[tid] = a2[tid];
    __syncthreads();

    for (int t = tid; t < HH * NN; t += 256) {
        int hd = t >> 7, n = t & 127;
        float acc[8];
        #pragma unroll
        for (int d = 0; d < 8; d++) acc[d] = 0.f;
        const float* w = sW + hd * (GG * DD);
        const float* x = sy + n * 49;
        #pragma unroll
        for (int f = 0; f < GG; f++) {
            float xv = x[f];
            #pragma unroll
            for (int d = 0; d < 8; d++) acc[d] = fmaf(xv, w[(f << 3) + d], acc[d]);
        }
        const float* av = sa + (hd << 4);
        float ei = 0.f, ej = 0.f;
        #pragma unroll
        for (int d = 0; d < 8; d++) { ei = fmaf(acc[d], av[d], ei); ej = fmaf(acc[d], av[8 + d], ej); }
        #pragma unroll
        for (int d = 0; d < 8; d++) sh[(t << 3) + d] = acc[d];
        sei[t] = ei; sej[t] = ej;
        sPj[t] = __expf(ej); sQj[t] = __expf(0.01f * ej);
    }
    __syncthreads();
    gat_attention(sh, sei, sej, sPj, sQj, smask, sy, tid);
    __syncthreads();

    for (int t = tid; t < FF * GG; t += 256) sW[t] = Wr[t];
    if (tid < GG) sa[tid] = br[tid];
    __syncthreads();
    for (int t = tid; t < XG; t += 256) {
        int n = t / 48, c = t - n * 48;
        float accv = sa[c];
        const float* x = sX + n * 17;
        #pragma unroll
        for (int f = 0; f < FF; f++) accv = fmaf(x[f], sW[f * 48 + c], accv);
        sy[n * 49 + c] += accv;
    }
    __syncthreads();
    ln2d_apply(sy, g2, b2, sred, tid, g_x + (size_t)b * XG);
}

// =======================================================================
// Double-buffered 3xTF32 GEMM, B row-major [N,K] (bTrans=0 case only).
// C_part[M,N] = A[M,K-slice] @ B^T (+bias if given, relu if act).
// grid.z = split-K part; each part handles kChunk and writes C + z*M*N.
// BM=BN=64, BK=32, 256 thr / 8 warps (4x2), warp tile 16x32.
// Dynamic smem: 2 bufs x (A,B) x (hi,lo) x 64x36 u32 = 73728 B.
// =======================================================================
#define PLANE_W  (64*36)              // words per plane
#define BUF_W    (2*PLANE_W)          // words per (hi,lo) buffer
#define LO_BYTES (PLANE_W*4)
#define BUF_BYTES (BUF_W*4)

__global__ __launch_bounds__(256)
void gemm_nk(const float* __restrict__ Af, const float* __restrict__ Bf,
             const float* __restrict__ bias, float* __restrict__ C,
             int M, int N, int K, int kChunk, int act)
{
    extern __shared__ uint32_t smem[];
    uint32_t* sA = smem;                 // [2][2][64][36]
    uint32_t* sB = smem + 2 * BUF_W;

    int tid  = threadIdx.x;
    int lane = tid & 31, wid = tid >> 5;
    int warpM = (wid >> 1) << 4;
    int warpN = (wid & 1) << 5;
    int g = lane >> 2, tig = lane & 3;
    int bm = blockIdx.y << 6, bn = blockIdx.x << 6;
    int kBeg = blockIdx.z * kChunk;
    int nt   = kChunk >> 5;

    uint32_t aOff = (((warpM + (lane & 15)) * 36 + ((lane >> 4) << 2)) << 2);
    uint32_t bOff = (((warpN + ((lane >> 4) << 3) + (lane & 7)) * 36 + (((lane >> 3) & 1) << 2)) << 2);
    uint32_t aBaseS = smem_u32(sA);
    uint32_t bBaseS = smem_u32(sB);

    int frow = tid >> 3;                 // +32 for q=1
    int fkc  = (tid & 7) << 2;

    float acc[4][4];
    #pragma unroll
    for (int ns = 0; ns < 4; ns++)
        #pragma unroll
        for (int r = 0; r < 4; r++) acc[ns][r] = 0.f;

    float4 pA[2], pB[2];

    // fetch tile at k-offset kt (relative to kBeg)
    auto FETCH = [&](int kt) {
        #pragma unroll
        for (int q = 0; q < 2; q++) {
            int row = frow + (q << 5);
            const float* ap = Af + (size_t)(bm + row) * K + kBeg + kt + fkc;
            const float* bp = Bf + (size_t)(bn + row) * K + kBeg + kt + fkc;
            pA[q] = *(const float4*)ap;
            pB[q] = *(const float4*)bp;
        }
    };
    auto STORE = [&](int buf) {
        uint32_t* dA = sA + buf * BUF_W;
        uint32_t* dB = sB + buf * BUF_W;
        #pragma unroll
        for (int q = 0; q < 2; q++) {
            int row = frow + (q << 5);
            uint4 hi, lo;
            tf32split(pA[q].x, hi.x, lo.x); tf32split(pA[q].y, hi.y, lo.y);
            tf32split(pA[q].z, hi.z, lo.z); tf32split(pA[q].w, hi.w, lo.w);
            *(uint4*)(dA + row * 36 + fkc)           = hi;
            *(uint4*)(dA + PLANE_W + row * 36 + fkc) = lo;
            tf32split(pB[q].x, hi.x, lo.x); tf32split(pB[q].y, hi.y, lo.y);
            tf32split(pB[q].z, hi.z, lo.z); tf32split(pB[q].w, hi.w, lo.w);
            *(uint4*)(dB + row * 36 + fkc)           = hi;
            *(uint4*)(dB + PLANE_W + row * 36 + fkc) = lo;
        }
    };

    FETCH(0);
    STORE(0);
    __syncthreads();

    for (int t = 0; t < nt; t++) {
        int cur = t & 1;
        bool more = (t + 1 < nt);
        if (more) FETCH((t + 1) << 5);

        uint32_t aB  = aBaseS + cur * BUF_BYTES + aOff;
        uint32_t bB0 = bBaseS + cur * BUF_BYTES + bOff;
        uint32_t bB1 = bB0 + ((16 * 36) << 2);
        #pragma unroll
        for (int ks = 0; ks < 4; ks++) {
            uint32_t koff = (ks << 3) << 2;
            uint32_t ah[4], al[4], bh[2][4], bl[2][4];
            ldsm_x4(ah, aB + koff);
            ldsm_x4(al, aB + LO_BYTES + koff);
            ldsm_x4(bh[0], bB0 + koff);
            ldsm_x4(bl[0], bB0 + LO_BYTES + koff);
            ldsm_x4(bh[1], bB1 + koff);
            ldsm_x4(bl[1], bB1 + LO_BYTES + koff);
            #pragma unroll
            for (int p = 0; p < 2; p++)
                #pragma unroll
                for (int half = 0; half < 2; half++) {
                    int ns = (p << 1) + half;
                    const uint32_t bfh[2] = {bh[p][half << 1], bh[p][(half << 1) + 1]};
                    const uint32_t bfl[2] = {bl[p][half << 1], bl[p][(half << 1) + 1]};
                    mma_tf32(acc[ns], ah, bfh);
                    mma_tf32(acc[ns], ah, bfl);
                    mma_tf32(acc[ns], al, bfh);
                }
        }
        if (more) STORE(cur ^ 1);
        __syncthreads();
    }

    float* Cp = C + (size_t)blockIdx.z * M * N;
    int r0 = bm + warpM + g;
    #pragma unroll
    for (int ns = 0; ns < 4; ns++) {
        int c0 = bn + warpN + (ns << 3) + (tig << 1);
        float b0v = bias ? bias[c0] : 0.f;
        float b1v = bias ? bias[c0 + 1] : 0.f;
        float v0 = acc[ns][0] + b0v, v1 = acc[ns][1] + b1v;
        float v2 = acc[ns][2] + b0v, v3 = acc[ns][3] + b1v;
        if (act) {
            v0 = fmaxf(v0, 0.f); v1 = fmaxf(v1, 0.f);
            v2 = fmaxf(v2, 0.f); v3 = fmaxf(v3, 0.f);
        }
        size_t o0 = (size_t)r0 * N + c0, o2 = (size_t)(r0 + 8) * N + c0;
        Cp[o0] = v0; Cp[o0 + 1] = v1; Cp[o2] = v2; Cp[o2 + 1] = v3;
    }
}

// =======================================================================
// Single-buffer GEMM for transposed-B (B row-major [K,N]) — R4 kernel.
// =======================================================================
__global__ __launch_bounds__(256)
void gemm_t(const float* __restrict__ Af, const float* __restrict__ Bf,
            const float* __restrict__ bias, float* __restrict__ C,
            int M, int N, int K, int ldb, int act)
{
    __shared__ uint32_t sA[2][64][36];
    __shared__ uint32_t sB[2][64][36];

    int tid  = threadIdx.x;
    int lane = tid & 31, wid = tid >> 5;
    int warpM = (wid >> 1) << 4;
    int warpN = (wid & 1) << 5;
    int g = lane >> 2, tig = lane & 3;
    int bm = blockIdx.y << 6, bn = blockIdx.x << 6;

    uint32_t aBase = smem_u32(&sA[0][0][0]) +
        (((warpM + (lane & 15)) * 36 + ((lane >> 4) << 2)) << 2);
    uint32_t bBase0 = smem_u32(&sB[0][0][0]) +
        (((warpN + ((lane >> 4) << 3) + (lane & 7)) * 36 + (((lane >> 3) & 1) << 2)) << 2);
    uint32_t bBase1 = bBase0 + (16 * 36 << 2);
    const uint32_t LO = (64 * 36) << 2;

    float acc[4][4];
    #pragma unroll
    for (int ns = 0; ns < 4; ns++)
        #pragma unroll
        for (int r = 0; r < 4; r++) acc[ns][r] = 0.f;

    float4 pA[2], pB[2];
    #pragma unroll
    for (int q = 0; q < 2; q++) {
        int idx = tid + (q << 8);
        int row = idx >> 3, kc = (idx & 7) << 2;
        pA[q] = *(const float4*)(Af + (size_t)(bm + row) * K + kc);
        int k = idx >> 4, n0 = (idx & 15) << 2;
        pB[q] = *(const float4*)(Bf + (size_t)k * ldb + bn + n0);
    }

    for (int kt = 0; kt < K; kt += 32) {
        #pragma unroll
        for (int q = 0; q < 2; q++) {
            int idx = tid + (q << 8);
            {
                int row = idx >> 3, kc = (idx & 7) << 2;
                uint4 hi, lo;
                tf32split(pA[q].x, hi.x, lo.x); tf32split(pA[q].y, hi.y, lo.y);
                tf32split(pA[q].z, hi.z, lo.z); tf32split(pA[q].w, hi.w, lo.w);
                *(uint4*)&sA[0][row][kc] = hi;
                *(uint4*)&sA[1][row][kc] = lo;
            }
            {
                int k = idx >> 4, n0 = (idx & 15) << 2;
                float v[4] = {pB[q].x, pB[q].y, pB[q].z, pB[q].w};
                #pragma unroll
                for (int j = 0; j < 4; j++) {
                    uint32_t hb, lb; tf32split(v[j], hb, lb);
                    sB[0][n0 + j][k] = hb; sB[1][n0 + j][k] = lb;
                }
            }
        }
        __syncthreads();

        int ktn = kt + 32;
        if (ktn < K) {
            #pragma unroll
            for (int q = 0; q < 2; q++) {
                int idx = tid + (q << 8);
                int row = idx >> 3, kc = (idx & 7) << 2;
                pA[q] = *(const float4*)(Af + (size_t)(bm + row) * K + ktn + kc);
                int k = idx >> 4, n0 = (idx & 15) << 2;
                pB[q] = *(const float4*)(Bf + (size_t)(ktn + k) * ldb + bn + n0);
            }
        }

        #pragma unroll
        for (int ks = 0; ks < 4; ks++) {
            uint32_t koff = (ks << 3) << 2;
            uint32_t ah[4], al[4], bh[2][4], bl[2][4];
            ldsm_x4(ah, aBase + koff);
            ldsm_x4(al, aBase + LO + koff);
            ldsm_x4(bh[0], bBase0 + koff);
            ldsm_x4(bl[0], bBase0 + LO + koff);
            ldsm_x4(bh[1], bBase1 + koff);
            ldsm_x4(bl[1], bBase1 + LO + koff);
            #pragma unroll
            for (int p = 0; p < 2; p++)
                #pragma unroll
                for (int half = 0; half < 2; half++) {
                    int ns = (p << 1) + half;
                    const uint32_t bfh[2] = {bh[p][half << 1], bh[p][(half << 1) + 1]};
                    const uint32_t bfl[2] = {bl[p][half << 1], bl[p][(half << 1) + 1]};
                    mma_tf32(acc[ns], ah, bfh);
                    mma_tf32(acc[ns], ah, bfl);
                    mma_tf32(acc[ns], al, bfh);
                }
        }
        __syncthreads();
    }

    int r0 = bm + warpM + g;
    #pragma unroll
    for (int ns = 0; ns < 4; ns++) {
        int c0 = bn + warpN + (ns << 3) + (tig << 1);
        float b0v = bias[c0], b1v = bias[c0 + 1];
        float v0 = acc[ns][0] + b0v, v1 = acc[ns][1] + b1v;
        float v2 = acc[ns][2] + b0v, v3 = acc[ns][3] + b1v;
        if (act) {
            v0 = fmaxf(v0, 0.f); v1 = fmaxf(v1, 0.f);
            v2 = fmaxf(v2, 0.f); v3 = fmaxf(v3, 0.f);
        }
        size_t o0 = (size_t)r0 * N + c0, o2 = (size_t)(r0 + 8) * N + c0;
        C[o0] = v0; C[o0 + 1] = v1; C[o2] = v2; C[o2 + 1] = v3;
    }
}

// =======================================================================
// GRU gates, layer 0: reduce SPLITK partials + bih + bhh; h = (1-z)*n
// =======================================================================
__global__ __launch_bounds__(256)
void gru_gates0(const float* __restrict__ gip, const float* __restrict__ bih,
                const float* __restrict__ bhh, float* __restrict__ h)
{
    int idx = blockIdx.x * 256 + threadIdx.x;
    int b = idx >> 8, j = idx & 255;
    const float* g0 = gip + (size_t)b * G3;
    const size_t P = (size_t)BB * G3;
    float vr = bih[j], vz = bih[256 + j], vn = bih[512 + j];
    #pragma unroll
    for (int s = 0; s < SPLITK; s++) {
        vr += g0[s * P + j];
        vz += g0[s * P + 256 + j];
        vn += g0[s * P + 512 + j];
    }
    float r = 1.f / (1.f + __expf(-(vr + bhh[j])));
    float z = 1.f / (1.f + __expf(-(vz + bhh[256 + j])));
    float n = tanhf(vn + r * bhh[512 + j]);
    h[idx] = (1.f - z) * n;
}

// GRU gates, layers 1/2: gi already includes bih
__global__ __launch_bounds__(256)
void gru_gates(const float* __restrict__ gi, const float* __restrict__ bhh,
               float* __restrict__ h)
{
    int idx = blockIdx.x * 256 + threadIdx.x;
    int b = idx >> 8, j = idx & 255;
    const float* g = gi + (size_t)b * G3;
    float r = 1.f / (1.f + __expf(-(g[j]       + bhh[j])));
    float z = 1.f / (1.f + __expf(-(g[256 + j] + bhh[256 + j])));
    float n = tanhf(g[512 + j] + r * bhh[512 + j]);
    h[idx] = (1.f - z) * n;
}

// =======================================================================
// LayerNorm over GRU dim
// =======================================================================
__global__ __launch_bounds__(256)
void ln1d_k(const float* __restrict__ h, const float* __restrict__ g,
            const float* __restrict__ b, float* __restrict__ o)
{
    __shared__ float s1[8], s2[8], mv[2];
    int row = blockIdx.x, tid = threadIdx.x;
    float v = h[(size_t)row * GRUU + tid];
    float s = v, q = v * v;
    #pragma unroll
    for (int off = 16; off; off >>= 1) {
        s += __shfl_xor_sync(0xffffffffu, s, off);
        q += __shfl_xor_sync(0xffffffffu, q, off);
    }
    if ((tid & 31) == 0) { s1[tid >> 5] = s; s2[tid >> 5] = q; }
    __syncthreads();
    if (tid == 0) {
        float S = 0.f, Q = 0.f;
        #pragma unroll
        for (int i = 0; i < 8; i++) { S += s1[i]; Q += s2[i]; }
        float m = S * (1.f / 256.f);
        float var = Q * (1.f / 256.f) - m * m;
        mv[0] = m; mv[1] = rsqrtf(var + 1e-5f);
    }
    __syncthreads();
    o[(size_t)row * GRUU + tid] = (v - mv[0]) * mv[1] * g[tid] + b[tid];
}

// =======================================================================
// host launcher
// =======================================================================
extern "C" void kernel_launch(void* const* d_in, const int* in_sizes, int n_in,
                              void* d_out, int out_size)
{
    const float* X    = (const float*)d_in[0];
    const int*   A    = (const int*)  d_in[1];
    const float* W1   = (const float*)d_in[2];
    const float* a1   = (const float*)d_in[3];
    const float* W2   = (const float*)d_in[4];
    const float* a2   = (const float*)d_in[5];
    const float* Wr   = (const float*)d_in[6];
    const float* br   = (const float*)d_in[7];
    const float* g1   = (const float*)d_in[8];
    const float* b1   = (const float*)d_in[9];
    const float* g2   = (const float*)d_in[10];
    const float* b2   = (const float*)d_in[11];
    const float* Wih0 = (const float*)d_in[12];
    const float* bih0 = (const float*)d_in[14];
    const float* bhh0 = (const float*)d_in[15];
    const float* Wih1 = (const float*)d_in[16];
    const float* bih1 = (const float*)d_in[18];
    const float* bhh1 = (const float*)d_in[19];
    const float* Wih2 = (const float*)d_in[20];
    const float* bih2 = (const float*)d_in[22];
    const float* bhh2 = (const float*)d_in[23];
    const float* gng  = (const float*)d_in[24];
    const float* gnb  = (const float*)d_in[25];
    const float* We   = (const float*)d_in[26];
    const float* be   = (const float*)d_in[27];
    const float* Wp   = (const float*)d_in[28];
    const float* bp   = (const float*)d_in[29];
    float* out = (float*)d_out;

    float *px, *pgip, *ph, *phln, *pemb;
    cudaGetSymbolAddress((void**)&px,   g_x);
    cudaGetSymbolAddress((void**)&pgip, g_gip);
    cudaGetSymbolAddress((void**)&ph,   g_h);
    cudaGetSymbolAddress((void**)&phln, g_hln);
    cudaGetSymbolAddress((void**)&pemb, g_emb);

    const int GAT_SMEM = (2176 + 6144 + 6272 + 4 * 768 + 2304 + 96 + 20 + 512) * 4;
    cudaFuncSetAttribute(gat_kernel, cudaFuncAttributeMaxDynamicSharedMemorySize, GAT_SMEM);
    const int GEMM_SMEM = 2 * BUF_BYTES * 2;   // 73728
    cudaFuncSetAttribute(gemm_nk, cudaFuncAttributeMaxDynamicSharedMemorySize, GEMM_SMEM);

    gat_kernel<<<BB, 256, GAT_SMEM>>>(X, A, W1, a1, W2, a2, Wr, br, g1, b1, g2, b2);

    // GRU layer 0: split-K x4
    dim3 g0(G3 / 64, BB / 64, SPLITK);             // 12 x 16 x 4
    gemm_nk<<<g0, 256, GEMM_SMEM>>>(px, Wih0, nullptr, pgip,
                                    BB, G3, XG, XG / SPLITK, 0);
    gru_gates0<<<BB, 256>>>(pgip, bih0, bhh0, ph);

    // GRU layers 1 & 2
    dim3 g1d(G3 / 64, BB / 64, 1);
    gemm_nk<<<g1d, 256, GEMM_SMEM>>>(ph, Wih1, bih1, pgip, BB, G3, GRUU, GRUU, 0);
    gru_gates<<<BB, 256>>>(pgip, bhh1, ph);
    gemm_nk<<<g1d, 256, GEMM_SMEM>>>(ph, Wih2, bih2, pgip, BB, G3, GRUU, GRUU, 0);
    gru_gates<<<BB, 256>>>(pgip, bhh2, ph);

    ln1d_k<<<BB, 256>>>(ph, gng, gnb, phln);

    float* embp = (out_size >= 2 * BB * EMBB) ? (out + (size_t)BB * EMBB) : pemb;
    dim3 gEmb(EMBB / 64, BB / 64);
    gemm_t<<<gEmb, 256>>>(phln, We, be, embp, BB, EMBB, GRUU, EMBB, 1);

    dim3 gPred(NN / 64, BB / 64);
    gemm_t<<<gPred, 256>>>(embp, Wp, bp, out, BB, NN, EMBB, NN, 0);
}